// round 8
// baseline (speedup 1.0000x reference)
#include <cuda_runtime.h>
#include <cuda_bf16.h>
#include <math.h>
#include <stdint.h>

#define N_NODES 20000
#define N_EDGES 320000
#define NE_TOT  (N_EDGES + N_NODES)   /* 340000 incl self loops */
#define IN_CH   512
#define HID     128
#define HEADS   4
#define OUT_CH  256
#define L1_F    (HEADS * HID)         /* 512 */

#define A1_OFF  (N_NODES * OUT_CH)            /* 5,120,000 */
#define A2_OFF  (A1_OFF + NE_TOT * HEADS)     /* 6,480,000 */

/* ------------------------- scratch (device globals) ------------------------- */
__device__ float         g_h1[(size_t)N_NODES * L1_F];
__device__ float         g_h2[(size_t)N_NODES * OUT_CH];
__device__ __nv_bfloat16 g_xhi[(size_t)N_NODES * IN_CH];
__device__ __nv_bfloat16 g_xlo[(size_t)N_NODES * IN_CH];
__device__ __nv_bfloat16 g_w1hi[L1_F * IN_CH];      /* transposed [N][K] */
__device__ __nv_bfloat16 g_w1lo[L1_F * IN_CH];
__device__ __nv_bfloat16 g_w2hi[OUT_CH * L1_F];
__device__ __nv_bfloat16 g_w2lo[OUT_CH * L1_F];
__device__ __nv_bfloat16 g_a1hi[(size_t)N_NODES * L1_F];
__device__ __nv_bfloat16 g_a1lo[(size_t)N_NODES * L1_F];
__device__ float g_as1[N_NODES * HEADS];
__device__ float g_ad1[N_NODES * HEADS];
__device__ float g_as2[N_NODES];
__device__ float g_ad2[N_NODES];
__device__ float g_vbuf[(size_t)NE_TOT * HEADS];    /* [head][csr_pos] */
__device__ int   g_counts[N_NODES];
__device__ int   g_cursor[N_NODES];
__device__ int   g_rowptr[N_NODES + 1];
__device__ int   g_esrc[NE_TOT];
__device__ int   g_eorig[NE_TOT];

/* ------------------------- helpers ------------------------- */
__device__ __forceinline__ uint32_t smem_u32(const void* p) {
    uint32_t a;
    asm("{ .reg .u64 t; cvta.to.shared.u64 t, %1; cvt.u32.u64 %0, t; }" : "=r"(a) : "l"(p));
    return a;
}
__device__ __forceinline__ void ldsm_x4(uint32_t& r0, uint32_t& r1, uint32_t& r2,
                                        uint32_t& r3, uint32_t addr) {
    asm volatile("ldmatrix.sync.aligned.m8n8.x4.shared.b16 {%0,%1,%2,%3}, [%4];"
                 : "=r"(r0), "=r"(r1), "=r"(r2), "=r"(r3) : "r"(addr));
}
__device__ __forceinline__ void mma_bf16(float* d, const uint32_t* a, const uint32_t* b) {
    asm volatile("mma.sync.aligned.m16n8k16.row.col.f32.bf16.bf16.f32 "
                 "{%0,%1,%2,%3}, {%4,%5,%6,%7}, {%8,%9}, {%0,%1,%2,%3};"
                 : "+f"(d[0]), "+f"(d[1]), "+f"(d[2]), "+f"(d[3])
                 : "r"(a[0]), "r"(a[1]), "r"(a[2]), "r"(a[3]), "r"(b[0]), "r"(b[1]));
}
__device__ __forceinline__ void cpa16(uint32_t dst, const void* src) {
    asm volatile("cp.async.cg.shared.global [%0], [%1], 16;" :: "r"(dst), "l"(src));
}
#define CP_COMMIT() asm volatile("cp.async.commit_group;" ::: "memory")
#define CP_WAIT2()  asm volatile("cp.async.wait_group 2;" ::: "memory")

/* ------------------------- CSR construction ------------------------- */
__device__ __forceinline__ void edge_nodes(const int* __restrict__ ei, int e,
                                           int& src, int& dst) {
    if (e < N_EDGES) { src = ei[e]; dst = ei[N_EDGES + e]; }
    else             { src = dst = e - N_EDGES; }
}

__global__ void count_deg(const int* __restrict__ ei) {
    int e = blockIdx.x * blockDim.x + threadIdx.x;
    if (e >= NE_TOT) return;
    int src, dst;
    edge_nodes(ei, e, src, dst);
    atomicAdd(&g_counts[dst], 1);
}

__global__ void scan_rowptr() {
    __shared__ int wsum[32];
    __shared__ int s_carry;
    int tid = threadIdx.x, lane = tid & 31, wid = tid >> 5;
    if (tid == 0) { g_rowptr[0] = 0; s_carry = 0; }
    __syncthreads();
    for (int base = 0; base < N_NODES; base += 1024) {
        int i = base + tid;
        int v = (i < N_NODES) ? g_counts[i] : 0;
        int x = v;
#pragma unroll
        for (int o = 1; o < 32; o <<= 1) {
            int t = __shfl_up_sync(0xFFFFFFFFu, x, o);
            if (lane >= o) x += t;
        }
        if (lane == 31) wsum[wid] = x;
        __syncthreads();
        if (wid == 0) {
            int s = wsum[lane];
#pragma unroll
            for (int o = 1; o < 32; o <<= 1) {
                int t = __shfl_up_sync(0xFFFFFFFFu, s, o);
                if (lane >= o) s += t;
            }
            wsum[lane] = s;
        }
        __syncthreads();
        int inc = x + (wid > 0 ? wsum[wid - 1] : 0) + s_carry;
        if (i < N_NODES) g_rowptr[i + 1] = inc;
        __syncthreads();
        if (tid == 1023) s_carry = inc;
        __syncthreads();
    }
}

__global__ void scatter_edges(const int* __restrict__ ei) {
    int e = blockIdx.x * blockDim.x + threadIdx.x;
    if (e >= NE_TOT) return;
    int src, dst;
    edge_nodes(ei, e, src, dst);
    int pos = g_rowptr[dst] + atomicAdd(&g_cursor[dst], 1);
    g_esrc[pos]  = src;
    g_eorig[pos] = e;
}

/* ------------------------- fp32 -> bf16 hi/lo splits ------------------------- */
/* also zeroes CSR counters */
__global__ void split_fp32_zero(const float* __restrict__ in,
                                __nv_bfloat16* __restrict__ hi,
                                __nv_bfloat16* __restrict__ lo, int n) {
    int i = blockIdx.x * blockDim.x + threadIdx.x;
    if (i < N_NODES) { g_counts[i] = 0; g_cursor[i] = 0; }
    if (i >= n) return;
    float v = in[i];
    __nv_bfloat16 h = __float2bfloat16(v);
    hi[i] = h;
    lo[i] = __float2bfloat16(v - __bfloat162float(h));
}

/* W [K][N] -> out [N][K] bf16 hi/lo */
__global__ void split_w_t(const float* __restrict__ W,
                          __nv_bfloat16* __restrict__ thi,
                          __nv_bfloat16* __restrict__ tlo, int K, int N) {
    int i = blockIdx.x * blockDim.x + threadIdx.x;
    if (i >= K * N) return;
    int k = i / N, n = i % N;
    float v = W[i];
    __nv_bfloat16 h = __float2bfloat16(v);
    thi[n * K + k] = h;
    tlo[n * K + k] = __float2bfloat16(v - __bfloat162float(h));
}

/* ------------------------- HMMA bf16-split GEMM -------------------------
   K-extended: C = [Ahi|Alo|Ahi] . [Bhi|Bhi|Blo]^T over 48 k32 stages
   (3 passes x 16 chunks). One A plane + one B plane per stage.
   k32 per stage = 2 k16 sub-steps per barrier: 32 MMAs/warp between syncs.
   4-buffer cp.async pipeline (96 KB dynamic smem), prefetch distance 2.
   __launch_bounds__(256,2) => <=128 regs => 2 CTAs/SM (192 KB smem / SM). */
#define NSTAGE 48
#define SROW   24
#define RB     (SROW * 2)              /* 48B row stride */
#define SUBB   (128 * RB)              /* 6144B per k16 sub-plane */
#define BUFB   (2 * SUBB)              /* 12288B per k32 buffer */
#define ASIZE  (4 * BUFB)              /* 49152 */
#define SMEM_DYN (2 * ASIZE)           /* 98304 */

__global__ __launch_bounds__(256, 2)
void gemm_hmma(const __nv_bfloat16* __restrict__ Ahi, const __nv_bfloat16* __restrict__ Alo,
               const __nv_bfloat16* __restrict__ Bhi, const __nv_bfloat16* __restrict__ Blo,
               float* __restrict__ C, int M, int N) {
    extern __shared__ __align__(16) char smem[];
    uint32_t sa0 = smem_u32(smem);             /* A planes */
    uint32_t sb0 = sa0 + ASIZE;                /* B planes */

    int tid = threadIdx.x, wid = tid >> 5, lane = tid & 31;
    int m0 = blockIdx.y * 128, n0 = blockIdx.x * 128;
    int wm = (wid >> 1) * 32;
    int wn = (wid & 1) * 64;

    /* gmem load coords: thread loads one 16B chunk per sub-plane per stage */
    int prow = tid >> 1, pseg = tid & 1;
    int agr = m0 + prow; if (agr >= M) agr = M - 1;
    const __nv_bfloat16* bAhi = Ahi + (size_t)agr * 512 + pseg * 8;
    const __nv_bfloat16* bAlo = Alo + (size_t)agr * 512 + pseg * 8;
    const __nv_bfloat16* bBhi = Bhi + (size_t)(n0 + prow) * 512 + pseg * 8;
    const __nv_bfloat16* bBlo = Blo + (size_t)(n0 + prow) * 512 + pseg * 8;
    uint32_t dstA = sa0 + prow * RB + pseg * 16;
    uint32_t dstB = sb0 + prow * RB + pseg * 16;

    /* ldmatrix lane addresses (within sub-plane 0 of buffer 0) */
    int a_row = (lane & 15), a_k = (lane >> 4) * 8;
    int b_nrow = ((lane >> 4) << 3) + (lane & 7), b_k = ((lane >> 3) & 1) * 8;
    uint32_t a_base = sa0 + (wm + a_row) * RB + a_k * 2;
    uint32_t b_base = sb0 + (wn + b_nrow) * RB + b_k * 2;

    float acc[2][8][4];
#pragma unroll
    for (int i = 0; i < 2; i++)
#pragma unroll
        for (int j = 0; j < 8; j++)
#pragma unroll
            for (int q = 0; q < 4; q++) acc[i][j][q] = 0.f;

    /* prefetch stages 0,1 (both pass 0: Ahi/Bhi), one commit group per stage */
#pragma unroll
    for (int s = 0; s < 2; s++) {
#pragma unroll
        for (int sub = 0; sub < 2; sub++) {
            int ko = s * 32 + sub * 16;
            cpa16(dstA + s * BUFB + sub * SUBB, bAhi + ko);
            cpa16(dstB + s * BUFB + sub * SUBB, bBhi + ko);
        }
        CP_COMMIT();
    }

    for (int t = 0; t < NSTAGE; t++) {
        int buf = t & 3;
        /* prefetch stage t+2 */
        {
            int s = t + 2;
            if (s < NSTAGE) {
                int p = s >> 4, kc = s & 15;
                const __nv_bfloat16* pa = (p == 1) ? bAlo : bAhi;
                const __nv_bfloat16* pb = (p == 2) ? bBlo : bBhi;
#pragma unroll
                for (int sub = 0; sub < 2; sub++) {
                    int ko = kc * 32 + sub * 16;
                    cpa16(dstA + (s & 3) * BUFB + sub * SUBB, pa + ko);
                    cpa16(dstB + (s & 3) * BUFB + sub * SUBB, pb + ko);
                }
            }
            CP_COMMIT();
        }
        CP_WAIT2();
        __syncthreads();

#pragma unroll
        for (int sub = 0; sub < 2; sub++) {
            uint32_t off = buf * BUFB + sub * SUBB;
            uint32_t af[2][4];
#pragma unroll
            for (int ma = 0; ma < 2; ma++)
                ldsm_x4(af[ma][0], af[ma][1], af[ma][2], af[ma][3],
                        a_base + off + ma * 16 * RB);
            uint32_t bf[4][4];
#pragma unroll
            for (int g = 0; g < 4; g++)
                ldsm_x4(bf[g][0], bf[g][1], bf[g][2], bf[g][3],
                        b_base + off + g * 16 * RB);

#pragma unroll
            for (int ma = 0; ma < 2; ma++)
#pragma unroll
                for (int g = 0; g < 4; g++)
#pragma unroll
                    for (int h = 0; h < 2; h++)
                        mma_bf16(acc[ma][g * 2 + h], af[ma], &bf[g][h * 2]);
        }
    }

    /* epilogue: write fp32 C */
    int lg = lane >> 2, lt = lane & 3;
#pragma unroll
    for (int ma = 0; ma < 2; ma++) {
        int mrow0 = m0 + wm + ma * 16 + lg;
#pragma unroll
        for (int nb = 0; nb < 8; nb++) {
            int n = n0 + wn + nb * 8 + lt * 2;
            float* d = acc[ma][nb];
            if (mrow0 < M)
                *(float2*)(C + (size_t)mrow0 * N + n) = make_float2(d[0], d[1]);
            if (mrow0 + 8 < M)
                *(float2*)(C + (size_t)(mrow0 + 8) * N + n) = make_float2(d[2], d[3]);
        }
    }
}

/* ------------------------- attention coefficients ------------------------- */
template <int H, int C>
__global__ void attn_coef(const float* __restrict__ h,
                          const float* __restrict__ a_src,
                          const float* __restrict__ a_dst,
                          float* __restrict__ as, float* __restrict__ ad) {
    int gw = (blockIdx.x * blockDim.x + threadIdx.x) >> 5;
    int lane = threadIdx.x & 31;
    if (gw >= N_NODES * H) return;
    int n = gw / H, hh = gw % H;
    const float* hp = h + (size_t)n * (H * C) + hh * C;
    const float* sp = a_src + hh * C;
    const float* dp = a_dst + hh * C;
    float s = 0.f, d = 0.f;
#pragma unroll
    for (int c = lane; c < C; c += 32) {
        float v = hp[c];
        s += v * sp[c];
        d += v * dp[c];
    }
#pragma unroll
    for (int o = 16; o; o >>= 1) {
        s += __shfl_xor_sync(0xFFFFFFFFu, s, o);
        d += __shfl_xor_sync(0xFFFFFFFFu, d, o);
    }
    if (lane == 0) { as[gw] = s; ad[gw] = d; }
}

/* ------------------------- fused softmax + aggregate ------------------------- */
template <int H, int C, bool ELU, bool SPLIT>
__global__ __launch_bounds__(256)
void fused_agg(const float* __restrict__ as, const float* __restrict__ ad,
               const float* __restrict__ hfeat, const float* __restrict__ bias,
               float* __restrict__ alpha_out, float* __restrict__ aggout,
               __nv_bfloat16* __restrict__ ohi, __nv_bfloat16* __restrict__ olo) {
    int gw = (blockIdx.x * blockDim.x + threadIdx.x) >> 5;
    int lane = threadIdx.x & 31;
    if (gw >= N_NODES * H) return;
    int dst = gw / H, hh = gw % H;

    int beg = g_rowptr[dst], end = g_rowptr[dst + 1];
    float adv = ad[dst * H + hh];
    float* vb = g_vbuf + (size_t)hh * NE_TOT;

    /* pass 1: gather logits once, store contiguously, track max */
    float mx = -1e30f;
    for (int i = beg + lane; i < end; i += 32) {
        float v = as[g_esrc[i] * H + hh] + adv;
        v = v > 0.f ? v : 0.2f * v;
        vb[i] = v;
        mx = fmaxf(mx, v);
    }
#pragma unroll
    for (int o = 16; o; o >>= 1) mx = fmaxf(mx, __shfl_xor_sync(0xFFFFFFFFu, mx, o));

    /* pass 2: denom from contiguous buffer */
    float sm = 0.f;
    for (int i = beg + lane; i < end; i += 32) sm += __expf(vb[i] - mx);
#pragma unroll
    for (int o = 16; o; o >>= 1) sm += __shfl_xor_sync(0xFFFFFFFFu, sm, o);
    float inv = 1.f / sm;

    /* pass 3: alpha + gather-accumulate (software pipelined, depth 2) */
    constexpr int R = C / 128;
    float4 acc[R];
#pragma unroll
    for (int r = 0; r < R; r++) acc[r] = make_float4(0.f, 0.f, 0.f, 0.f);

    int i = beg;
    int s = g_esrc[i];
    int eo = g_eorig[i];
    float vv = vb[i];
    float4 tv[R];
    {
        const float4* hp = (const float4*)(hfeat + (size_t)s * (H * C) + hh * C);
#pragma unroll
        for (int r = 0; r < R; r++) tv[r] = hp[lane + 32 * r];
    }
    for (;;) {
        int inext = i + 1;
        bool more = inext < end;
        int s2 = 0, eo2 = 0;
        float vv2 = 0.f;
        float4 tv2[R];
        if (more) {
            s2 = g_esrc[inext];
            eo2 = g_eorig[inext];
            vv2 = vb[inext];
            const float4* hp2 = (const float4*)(hfeat + (size_t)s2 * (H * C) + hh * C);
#pragma unroll
            for (int r = 0; r < R; r++) tv2[r] = hp2[lane + 32 * r];
        }
        float a = __expf(vv - mx) * inv;
        if (lane == 0) alpha_out[eo * H + hh] = a;
#pragma unroll
        for (int r = 0; r < R; r++) {
            acc[r].x += a * tv[r].x;
            acc[r].y += a * tv[r].y;
            acc[r].z += a * tv[r].z;
            acc[r].w += a * tv[r].w;
        }
        if (!more) break;
        s = s2; eo = eo2; vv = vv2;
#pragma unroll
        for (int r = 0; r < R; r++) tv[r] = tv2[r];
        i = inext;
    }

    /* epilogue: bias (+ELU), fp32 out or bf16 hi/lo split */
#pragma unroll
    for (int r = 0; r < R; r++) {
        int c = (lane + 32 * r) * 4;
        const float* bp = bias + hh * C + c;
        float4 o = acc[r];
        o.x += bp[0]; o.y += bp[1]; o.z += bp[2]; o.w += bp[3];
        if (ELU) {
            o.x = o.x > 0.f ? o.x : expm1f(o.x);
            o.y = o.y > 0.f ? o.y : expm1f(o.y);
            o.z = o.z > 0.f ? o.z : expm1f(o.z);
            o.w = o.w > 0.f ? o.w : expm1f(o.w);
        }
        if (SPLIT) {
            size_t base = (size_t)dst * (H * C) + hh * C + c;
            float vv4[4] = { o.x, o.y, o.z, o.w };
#pragma unroll
            for (int q = 0; q < 4; q++) {
                __nv_bfloat16 h = __float2bfloat16(vv4[q]);
                ohi[base + q] = h;
                olo[base + q] = __float2bfloat16(vv4[q] - __bfloat162float(h));
            }
        } else {
            float* op = aggout + (size_t)dst * (H * C) + hh * C;
            ((float4*)op)[lane + 32 * r] = o;
        }
    }
}

/* ------------------------- launch ------------------------- */
extern "C" void kernel_launch(void* const* d_in, const int* in_sizes, int n_in,
                              void* d_out, int out_size) {
    const float* x      = (const float*)d_in[0];
    const int*   ei     = (const int*)  d_in[1];
    const float* W1     = (const float*)d_in[2];
    const float* a_src1 = (const float*)d_in[3];
    const float* a_dst1 = (const float*)d_in[4];
    const float* b1     = (const float*)d_in[5];
    const float* W2     = (const float*)d_in[6];
    const float* a_src2 = (const float*)d_in[7];
    const float* a_dst2 = (const float*)d_in[8];
    const float* b2     = (const float*)d_in[9];
    float* out = (float*)d_out;

    float *h1, *h2, *as1, *ad1, *as2, *ad2;
    __nv_bfloat16 *xhi, *xlo, *w1hi, *w1lo, *w2hi, *w2lo, *a1hi, *a1lo;
    cudaGetSymbolAddress((void**)&h1,   g_h1);
    cudaGetSymbolAddress((void**)&h2,   g_h2);
    cudaGetSymbolAddress((void**)&as1,  g_as1);
    cudaGetSymbolAddress((void**)&ad1,  g_ad1);
    cudaGetSymbolAddress((void**)&as2,  g_as2);
    cudaGetSymbolAddress((void**)&ad2,  g_ad2);
    cudaGetSymbolAddress((void**)&xhi,  g_xhi);
    cudaGetSymbolAddress((void**)&xlo,  g_xlo);
    cudaGetSymbolAddress((void**)&w1hi, g_w1hi);
    cudaGetSymbolAddress((void**)&w1lo, g_w1lo);
    cudaGetSymbolAddress((void**)&w2hi, g_w2hi);
    cudaGetSymbolAddress((void**)&w2lo, g_w2lo);
    cudaGetSymbolAddress((void**)&a1hi, g_a1hi);
    cudaGetSymbolAddress((void**)&a1lo, g_a1lo);

    cudaFuncSetAttribute(gemm_hmma, cudaFuncAttributeMaxDynamicSharedMemorySize, SMEM_DYN);

    /* 0-2: conversions (split_fp32_zero also zeroes CSR counters) */
    split_fp32_zero<<<(N_NODES * IN_CH + 255) / 256, 256>>>(x, xhi, xlo, N_NODES * IN_CH);
    split_w_t<<<(IN_CH * L1_F + 255) / 256, 256>>>(W1, w1hi, w1lo, IN_CH, L1_F);
    split_w_t<<<(L1_F * OUT_CH + 255) / 256, 256>>>(W2, w2hi, w2lo, L1_F, OUT_CH);

    /* 3: layer-1 GEMM (ncu capture slot) */
    gemm_hmma<<<dim3(L1_F / 128, 157), 256, SMEM_DYN>>>(xhi, xlo, w1hi, w1lo, h1, N_NODES, L1_F);

    /* 4-6: CSR build */
    count_deg<<<(NE_TOT + 255) / 256, 256>>>(ei);
    scan_rowptr<<<1, 1024>>>();
    scatter_edges<<<(NE_TOT + 255) / 256, 256>>>(ei);

    /* 7-8: layer-1 attention + aggregate */
    attn_coef<HEADS, HID><<<(N_NODES * HEADS + 7) / 8, 256>>>(h1, a_src1, a_dst1, as1, ad1);
    fused_agg<HEADS, HID, true, true><<<(N_NODES * HEADS + 7) / 8, 256>>>(
        as1, ad1, h1, b1, out + A1_OFF, nullptr, a1hi, a1lo);

    /* 9-11: layer 2 */
    gemm_hmma<<<dim3(OUT_CH / 128, 157), 256, SMEM_DYN>>>(a1hi, a1lo, w2hi, w2lo, h2, N_NODES, OUT_CH);
    attn_coef<1, OUT_CH><<<(N_NODES + 7) / 8, 256>>>(h2, a_src2, a_dst2, as2, ad2);
    fused_agg<1, OUT_CH, false, false><<<(N_NODES + 7) / 8, 256>>>(
        as2, ad2, h2, b2, out + A2_OFF, out, nullptr, nullptr);
}

// round 9
// speedup vs baseline: 1.0287x; 1.0287x over previous
#include <cuda_runtime.h>
#include <cuda_bf16.h>
#include <math.h>
#include <stdint.h>

#define N_NODES 20000
#define N_EDGES 320000
#define NE_TOT  (N_EDGES + N_NODES)   /* 340000 incl self loops */
#define IN_CH   512
#define HID     128
#define HEADS   4
#define OUT_CH  256
#define L1_F    (HEADS * HID)         /* 512 */

#define A1_OFF  (N_NODES * OUT_CH)            /* 5,120,000 */
#define A2_OFF  (A1_OFF + NE_TOT * HEADS)     /* 6,480,000 */

/* ------------------------- scratch (device globals) ------------------------- */
__device__ float         g_h1[(size_t)N_NODES * L1_F];
__device__ float         g_h2[(size_t)N_NODES * OUT_CH];
__device__ __nv_bfloat16 g_xhi[(size_t)N_NODES * IN_CH];
__device__ __nv_bfloat16 g_xlo[(size_t)N_NODES * IN_CH];
__device__ __nv_bfloat16 g_w1hi[L1_F * IN_CH];      /* transposed [N][K] */
__device__ __nv_bfloat16 g_w1lo[L1_F * IN_CH];
__device__ __nv_bfloat16 g_w2hi[OUT_CH * L1_F];
__device__ __nv_bfloat16 g_w2lo[OUT_CH * L1_F];
__device__ __nv_bfloat16 g_a1hi[(size_t)N_NODES * L1_F];
__device__ __nv_bfloat16 g_a1lo[(size_t)N_NODES * L1_F];
__device__ float g_as1[N_NODES * HEADS];
__device__ float g_ad1[N_NODES * HEADS];
__device__ float g_as2[N_NODES];
__device__ float g_ad2[N_NODES];
__device__ float g_vbuf[(size_t)NE_TOT * HEADS];    /* [head][csr_pos] */
__device__ int   g_counts[N_NODES];
__device__ int   g_cursor[N_NODES];
__device__ int   g_rowptr[N_NODES + 1];
__device__ int   g_esrc[NE_TOT];
__device__ int   g_eorig[NE_TOT];

/* ------------------------- helpers ------------------------- */
__device__ __forceinline__ uint32_t smem_u32(const void* p) {
    uint32_t a;
    asm("{ .reg .u64 t; cvta.to.shared.u64 t, %1; cvt.u32.u64 %0, t; }" : "=r"(a) : "l"(p));
    return a;
}
__device__ __forceinline__ void ldsm_x4(uint32_t& r0, uint32_t& r1, uint32_t& r2,
                                        uint32_t& r3, uint32_t addr) {
    asm volatile("ldmatrix.sync.aligned.m8n8.x4.shared.b16 {%0,%1,%2,%3}, [%4];"
                 : "=r"(r0), "=r"(r1), "=r"(r2), "=r"(r3) : "r"(addr));
}
__device__ __forceinline__ void mma_bf16(float* d, const uint32_t* a, const uint32_t* b) {
    asm volatile("mma.sync.aligned.m16n8k16.row.col.f32.bf16.bf16.f32 "
                 "{%0,%1,%2,%3}, {%4,%5,%6,%7}, {%8,%9}, {%0,%1,%2,%3};"
                 : "+f"(d[0]), "+f"(d[1]), "+f"(d[2]), "+f"(d[3])
                 : "r"(a[0]), "r"(a[1]), "r"(a[2]), "r"(a[3]), "r"(b[0]), "r"(b[1]));
}
__device__ __forceinline__ void cpa16(uint32_t dst, const void* src) {
    asm volatile("cp.async.cg.shared.global [%0], [%1], 16;" :: "r"(dst), "l"(src));
}
#define CP_COMMIT() asm volatile("cp.async.commit_group;" ::: "memory")
#define CP_WAIT1()  asm volatile("cp.async.wait_group 1;" ::: "memory")

/* ------------------------- CSR construction ------------------------- */
__device__ __forceinline__ void edge_nodes(const int* __restrict__ ei, int e,
                                           int& src, int& dst) {
    if (e < N_EDGES) { src = ei[e]; dst = ei[N_EDGES + e]; }
    else             { src = dst = e - N_EDGES; }
}

__global__ void count_deg(const int* __restrict__ ei) {
    int e = blockIdx.x * blockDim.x + threadIdx.x;
    if (e >= NE_TOT) return;
    int src, dst;
    edge_nodes(ei, e, src, dst);
    atomicAdd(&g_counts[dst], 1);
}

__global__ void scan_rowptr() {
    __shared__ int wsum[32];
    __shared__ int s_carry;
    int tid = threadIdx.x, lane = tid & 31, wid = tid >> 5;
    if (tid == 0) { g_rowptr[0] = 0; s_carry = 0; }
    __syncthreads();
    for (int base = 0; base < N_NODES; base += 1024) {
        int i = base + tid;
        int v = (i < N_NODES) ? g_counts[i] : 0;
        int x = v;
#pragma unroll
        for (int o = 1; o < 32; o <<= 1) {
            int t = __shfl_up_sync(0xFFFFFFFFu, x, o);
            if (lane >= o) x += t;
        }
        if (lane == 31) wsum[wid] = x;
        __syncthreads();
        if (wid == 0) {
            int s = wsum[lane];
#pragma unroll
            for (int o = 1; o < 32; o <<= 1) {
                int t = __shfl_up_sync(0xFFFFFFFFu, s, o);
                if (lane >= o) s += t;
            }
            wsum[lane] = s;
        }
        __syncthreads();
        int inc = x + (wid > 0 ? wsum[wid - 1] : 0) + s_carry;
        if (i < N_NODES) g_rowptr[i + 1] = inc;
        __syncthreads();
        if (tid == 1023) s_carry = inc;
        __syncthreads();
    }
}

__global__ void scatter_edges(const int* __restrict__ ei) {
    int e = blockIdx.x * blockDim.x + threadIdx.x;
    if (e >= NE_TOT) return;
    int src, dst;
    edge_nodes(ei, e, src, dst);
    int pos = g_rowptr[dst] + atomicAdd(&g_cursor[dst], 1);
    g_esrc[pos]  = src;
    g_eorig[pos] = e;
}

/* ------------------------- fp32 -> bf16 hi/lo splits ------------------------- */
/* also zeroes CSR counters */
__global__ void split_fp32_zero(const float* __restrict__ in,
                                __nv_bfloat16* __restrict__ hi,
                                __nv_bfloat16* __restrict__ lo, int n) {
    int i = blockIdx.x * blockDim.x + threadIdx.x;
    if (i < N_NODES) { g_counts[i] = 0; g_cursor[i] = 0; }
    if (i >= n) return;
    float v = in[i];
    __nv_bfloat16 h = __float2bfloat16(v);
    hi[i] = h;
    lo[i] = __float2bfloat16(v - __bfloat162float(h));
}

/* W [K][N] -> out [N][K] bf16 hi/lo */
__global__ void split_w_t(const float* __restrict__ W,
                          __nv_bfloat16* __restrict__ thi,
                          __nv_bfloat16* __restrict__ tlo, int K, int N) {
    int i = blockIdx.x * blockDim.x + threadIdx.x;
    if (i >= K * N) return;
    int k = i / N, n = i % N;
    float v = W[i];
    __nv_bfloat16 h = __float2bfloat16(v);
    thi[n * K + k] = h;
    tlo[n * K + k] = __float2bfloat16(v - __bfloat162float(h));
}

/* ------------------------- HMMA bf16-split GEMM -------------------------
   C[M,N] fp32 ≈ Ahi*Bhi^T + Alo*Bhi^T + Ahi*Blo^T; A [M,K], B [N,K] bf16.
   K=512, 32 k16 stages, BOTH hi+lo planes per stage, 48 MMAs/warp per sync.
   3-buffer cp.async pipeline, prefetch distance 2, wait_group<=1:
   barrier no longer serialized behind the in-flight prefetch's DRAM latency. */
#define KSTAGES (512 / 16)    /* 32 */
#define SROW    24
#define RB      (SROW * 2)            /* 48B row stride */
#define PLANEB  (128 * RB)            /* 6144B per plane */
#define BUFB    (2 * PLANEB)          /* 12288B per (hi,lo) buffer */
#define HALFB   (3 * BUFB)            /* 36864B: all A buffers */
#define SMEM_DYN (2 * HALFB)          /* 73728B */

__global__ __launch_bounds__(256)
void gemm_hmma(const __nv_bfloat16* __restrict__ Ahi, const __nv_bfloat16* __restrict__ Alo,
               const __nv_bfloat16* __restrict__ Bhi, const __nv_bfloat16* __restrict__ Blo,
               float* __restrict__ C, int M, int N) {
    extern __shared__ __align__(16) char smem[];
    uint32_t sa0 = smem_u32(smem);        /* A: [buf][plane][128][SROW] */
    uint32_t sb0 = sa0 + HALFB;           /* B: same layout */

    int tid = threadIdx.x, wid = tid >> 5, lane = tid & 31;
    int m0 = blockIdx.y * 128, n0 = blockIdx.x * 128;
    int wm = (wid >> 1) * 32;
    int wn = (wid & 1) * 64;

    /* gmem load coords: thread loads one 16B chunk per plane per stage */
    int prow = tid >> 1, pseg = tid & 1;
    int agr = m0 + prow; if (agr >= M) agr = M - 1;
    const __nv_bfloat16* pAhi = Ahi + (size_t)agr * 512 + pseg * 8;
    const __nv_bfloat16* pAlo = Alo + (size_t)agr * 512 + pseg * 8;
    const __nv_bfloat16* pBhi = Bhi + (size_t)(n0 + prow) * 512 + pseg * 8;
    const __nv_bfloat16* pBlo = Blo + (size_t)(n0 + prow) * 512 + pseg * 8;
    uint32_t dstA = sa0 + prow * RB + pseg * 16;
    uint32_t dstB = sb0 + prow * RB + pseg * 16;

    /* ldmatrix lane addresses */
    int a_row = (lane & 15), a_k = (lane >> 4) * 8;
    int b_nrow = ((lane >> 4) << 3) + (lane & 7), b_k = ((lane >> 3) & 1) * 8;
    uint32_t a_base = sa0 + (wm + a_row) * RB + a_k * 2;
    uint32_t b_base = sb0 + (wn + b_nrow) * RB + b_k * 2;

    float acc[2][8][4];
#pragma unroll
    for (int i = 0; i < 2; i++)
#pragma unroll
        for (int j = 0; j < 8; j++)
#pragma unroll
            for (int q = 0; q < 4; q++) acc[i][j][q] = 0.f;

    /* prologue: prefetch stages 0 and 1 (one commit group each) */
#pragma unroll
    for (int s = 0; s < 2; s++) {
        int ko = s * 16;
        cpa16(dstA + s * BUFB, pAhi + ko);
        cpa16(dstA + s * BUFB + PLANEB, pAlo + ko);
        cpa16(dstB + s * BUFB, pBhi + ko);
        cpa16(dstB + s * BUFB + PLANEB, pBlo + ko);
        CP_COMMIT();
    }

    int bufs[3] = { 0, BUFB, 2 * BUFB };
    for (int t = 0; t < KSTAGES; t++) {
        CP_WAIT1();               /* group t complete; group t+1 may fly */
        __syncthreads();

        uint32_t off = bufs[t % 3];
        uint32_t ahi[2][4], alo[2][4];
#pragma unroll
        for (int ma = 0; ma < 2; ma++) {
            ldsm_x4(ahi[ma][0], ahi[ma][1], ahi[ma][2], ahi[ma][3],
                    a_base + off + ma * 16 * RB);
            ldsm_x4(alo[ma][0], alo[ma][1], alo[ma][2], alo[ma][3],
                    a_base + off + PLANEB + ma * 16 * RB);
        }
        uint32_t bhi[4][4], blo[4][4];
#pragma unroll
        for (int g = 0; g < 4; g++) {
            ldsm_x4(bhi[g][0], bhi[g][1], bhi[g][2], bhi[g][3],
                    b_base + off + g * 16 * RB);
            ldsm_x4(blo[g][0], blo[g][1], blo[g][2], blo[g][3],
                    b_base + off + PLANEB + g * 16 * RB);
        }

#pragma unroll
        for (int ma = 0; ma < 2; ma++)
#pragma unroll
            for (int g = 0; g < 4; g++)
#pragma unroll
                for (int h = 0; h < 2; h++) {
                    float* d = acc[ma][g * 2 + h];
                    mma_bf16(d, ahi[ma], &bhi[g][h * 2]);
                    mma_bf16(d, alo[ma], &bhi[g][h * 2]);
                    mma_bf16(d, ahi[ma], &blo[g][h * 2]);
                }

        /* prefetch stage t+2 (overwrites buf (t+2)%3 = (t-1)%3; safe: the
           barrier above proves all threads finished reading it at t-1) */
        int s = t + 2;
        if (s < KSTAGES) {
            int ko = s * 16;
            uint32_t od = bufs[s % 3];
            cpa16(dstA + od, pAhi + ko);
            cpa16(dstA + od + PLANEB, pAlo + ko);
            cpa16(dstB + od, pBhi + ko);
            cpa16(dstB + od + PLANEB, pBlo + ko);
        }
        CP_COMMIT();
    }

    /* epilogue: write fp32 C */
    int lg = lane >> 2, lt = lane & 3;
#pragma unroll
    for (int ma = 0; ma < 2; ma++) {
        int mrow0 = m0 + wm + ma * 16 + lg;
#pragma unroll
        for (int nb = 0; nb < 8; nb++) {
            int n = n0 + wn + nb * 8 + lt * 2;
            float* d = acc[ma][nb];
            if (mrow0 < M)
                *(float2*)(C + (size_t)mrow0 * N + n) = make_float2(d[0], d[1]);
            if (mrow0 + 8 < M)
                *(float2*)(C + (size_t)(mrow0 + 8) * N + n) = make_float2(d[2], d[3]);
        }
    }
}

/* ------------------------- attention coefficients ------------------------- */
template <int H, int C>
__global__ void attn_coef(const float* __restrict__ h,
                          const float* __restrict__ a_src,
                          const float* __restrict__ a_dst,
                          float* __restrict__ as, float* __restrict__ ad) {
    int gw = (blockIdx.x * blockDim.x + threadIdx.x) >> 5;
    int lane = threadIdx.x & 31;
    if (gw >= N_NODES * H) return;
    int n = gw / H, hh = gw % H;
    const float* hp = h + (size_t)n * (H * C) + hh * C;
    const float* sp = a_src + hh * C;
    const float* dp = a_dst + hh * C;
    float s = 0.f, d = 0.f;
#pragma unroll
    for (int c = lane; c < C; c += 32) {
        float v = hp[c];
        s += v * sp[c];
        d += v * dp[c];
    }
#pragma unroll
    for (int o = 16; o; o >>= 1) {
        s += __shfl_xor_sync(0xFFFFFFFFu, s, o);
        d += __shfl_xor_sync(0xFFFFFFFFu, d, o);
    }
    if (lane == 0) { as[gw] = s; ad[gw] = d; }
}

/* ------------------------- fused softmax + aggregate ------------------------- */
template <int H, int C, bool ELU, bool SPLIT>
__global__ __launch_bounds__(256)
void fused_agg(const float* __restrict__ as, const float* __restrict__ ad,
               const float* __restrict__ hfeat, const float* __restrict__ bias,
               float* __restrict__ alpha_out, float* __restrict__ aggout,
               __nv_bfloat16* __restrict__ ohi, __nv_bfloat16* __restrict__ olo) {
    int gw = (blockIdx.x * blockDim.x + threadIdx.x) >> 5;
    int lane = threadIdx.x & 31;
    if (gw >= N_NODES * H) return;
    int dst = gw / H, hh = gw % H;

    int beg = g_rowptr[dst], end = g_rowptr[dst + 1];
    float adv = ad[dst * H + hh];
    float* vb = g_vbuf + (size_t)hh * NE_TOT;

    /* pass 1: gather logits once, store contiguously, track max */
    float mx = -1e30f;
    for (int i = beg + lane; i < end; i += 32) {
        float v = as[g_esrc[i] * H + hh] + adv;
        v = v > 0.f ? v : 0.2f * v;
        vb[i] = v;
        mx = fmaxf(mx, v);
    }
#pragma unroll
    for (int o = 16; o; o >>= 1) mx = fmaxf(mx, __shfl_xor_sync(0xFFFFFFFFu, mx, o));

    /* pass 2: denom from contiguous buffer */
    float sm = 0.f;
    for (int i = beg + lane; i < end; i += 32) sm += __expf(vb[i] - mx);
#pragma unroll
    for (int o = 16; o; o >>= 1) sm += __shfl_xor_sync(0xFFFFFFFFu, sm, o);
    float inv = 1.f / sm;

    /* pass 3: alpha + gather-accumulate (software pipelined, depth 2) */
    constexpr int R = C / 128;
    float4 acc[R];
#pragma unroll
    for (int r = 0; r < R; r++) acc[r] = make_float4(0.f, 0.f, 0.f, 0.f);

    int i = beg;
    int s = g_esrc[i];
    int eo = g_eorig[i];
    float vv = vb[i];
    float4 tv[R];
    {
        const float4* hp = (const float4*)(hfeat + (size_t)s * (H * C) + hh * C);
#pragma unroll
        for (int r = 0; r < R; r++) tv[r] = hp[lane + 32 * r];
    }
    for (;;) {
        int inext = i + 1;
        bool more = inext < end;
        int s2 = 0, eo2 = 0;
        float vv2 = 0.f;
        float4 tv2[R];
        if (more) {
            s2 = g_esrc[inext];
            eo2 = g_eorig[inext];
            vv2 = vb[inext];
            const float4* hp2 = (const float4*)(hfeat + (size_t)s2 * (H * C) + hh * C);
#pragma unroll
            for (int r = 0; r < R; r++) tv2[r] = hp2[lane + 32 * r];
        }
        float a = __expf(vv - mx) * inv;
        if (lane == 0) alpha_out[eo * H + hh] = a;
#pragma unroll
        for (int r = 0; r < R; r++) {
            acc[r].x += a * tv[r].x;
            acc[r].y += a * tv[r].y;
            acc[r].z += a * tv[r].z;
            acc[r].w += a * tv[r].w;
        }
        if (!more) break;
        s = s2; eo = eo2; vv = vv2;
#pragma unroll
        for (int r = 0; r < R; r++) tv[r] = tv2[r];
        i = inext;
    }

    /* epilogue: bias (+ELU), fp32 out or bf16 hi/lo split */
#pragma unroll
    for (int r = 0; r < R; r++) {
        int c = (lane + 32 * r) * 4;
        const float* bp = bias + hh * C + c;
        float4 o = acc[r];
        o.x += bp[0]; o.y += bp[1]; o.z += bp[2]; o.w += bp[3];
        if (ELU) {
            o.x = o.x > 0.f ? o.x : expm1f(o.x);
            o.y = o.y > 0.f ? o.y : expm1f(o.y);
            o.z = o.z > 0.f ? o.z : expm1f(o.z);
            o.w = o.w > 0.f ? o.w : expm1f(o.w);
        }
        if (SPLIT) {
            size_t base = (size_t)dst * (H * C) + hh * C + c;
            float vv4[4] = { o.x, o.y, o.z, o.w };
#pragma unroll
            for (int q = 0; q < 4; q++) {
                __nv_bfloat16 h = __float2bfloat16(vv4[q]);
                ohi[base + q] = h;
                olo[base + q] = __float2bfloat16(vv4[q] - __bfloat162float(h));
            }
        } else {
            float* op = aggout + (size_t)dst * (H * C) + hh * C;
            ((float4*)op)[lane + 32 * r] = o;
        }
    }
}

/* ------------------------- launch ------------------------- */
extern "C" void kernel_launch(void* const* d_in, const int* in_sizes, int n_in,
                              void* d_out, int out_size) {
    const float* x      = (const float*)d_in[0];
    const int*   ei     = (const int*)  d_in[1];
    const float* W1     = (const float*)d_in[2];
    const float* a_src1 = (const float*)d_in[3];
    const float* a_dst1 = (const float*)d_in[4];
    const float* b1     = (const float*)d_in[5];
    const float* W2     = (const float*)d_in[6];
    const float* a_src2 = (const float*)d_in[7];
    const float* a_dst2 = (const float*)d_in[8];
    const float* b2     = (const float*)d_in[9];
    float* out = (float*)d_out;

    float *h1, *h2, *as1, *ad1, *as2, *ad2;
    __nv_bfloat16 *xhi, *xlo, *w1hi, *w1lo, *w2hi, *w2lo, *a1hi, *a1lo;
    cudaGetSymbolAddress((void**)&h1,   g_h1);
    cudaGetSymbolAddress((void**)&h2,   g_h2);
    cudaGetSymbolAddress((void**)&as1,  g_as1);
    cudaGetSymbolAddress((void**)&ad1,  g_ad1);
    cudaGetSymbolAddress((void**)&as2,  g_as2);
    cudaGetSymbolAddress((void**)&ad2,  g_ad2);
    cudaGetSymbolAddress((void**)&xhi,  g_xhi);
    cudaGetSymbolAddress((void**)&xlo,  g_xlo);
    cudaGetSymbolAddress((void**)&w1hi, g_w1hi);
    cudaGetSymbolAddress((void**)&w1lo, g_w1lo);
    cudaGetSymbolAddress((void**)&w2hi, g_w2hi);
    cudaGetSymbolAddress((void**)&w2lo, g_w2lo);
    cudaGetSymbolAddress((void**)&a1hi, g_a1hi);
    cudaGetSymbolAddress((void**)&a1lo, g_a1lo);

    cudaFuncSetAttribute(gemm_hmma, cudaFuncAttributeMaxDynamicSharedMemorySize, SMEM_DYN);

    /* 0-2: conversions (split_fp32_zero also zeroes CSR counters) */
    split_fp32_zero<<<(N_NODES * IN_CH + 255) / 256, 256>>>(x, xhi, xlo, N_NODES * IN_CH);
    split_w_t<<<(IN_CH * L1_F + 255) / 256, 256>>>(W1, w1hi, w1lo, IN_CH, L1_F);
    split_w_t<<<(L1_F * OUT_CH + 255) / 256, 256>>>(W2, w2hi, w2lo, L1_F, OUT_CH);

    /* 3: layer-1 GEMM (ncu capture slot) */
    gemm_hmma<<<dim3(L1_F / 128, 157), 256, SMEM_DYN>>>(xhi, xlo, w1hi, w1lo, h1, N_NODES, L1_F);

    /* 4-6: CSR build */
    count_deg<<<(NE_TOT + 255) / 256, 256>>>(ei);
    scan_rowptr<<<1, 1024>>>();
    scatter_edges<<<(NE_TOT + 255) / 256, 256>>>(ei);

    /* 7-8: layer-1 attention + aggregate */
    attn_coef<HEADS, HID><<<(N_NODES * HEADS + 7) / 8, 256>>>(h1, a_src1, a_dst1, as1, ad1);
    fused_agg<HEADS, HID, true, true><<<(N_NODES * HEADS + 7) / 8, 256>>>(
        as1, ad1, h1, b1, out + A1_OFF, nullptr, a1hi, a1lo);

    /* 9-11: layer 2 */
    gemm_hmma<<<dim3(OUT_CH / 128, 157), 256, SMEM_DYN>>>(a1hi, a1lo, w2hi, w2lo, h2, N_NODES, OUT_CH);
    attn_coef<1, OUT_CH><<<(N_NODES + 7) / 8, 256>>>(h2, a_src2, a_dst2, as2, ad2);
    fused_agg<1, OUT_CH, false, false><<<(N_NODES + 7) / 8, 256>>>(
        as2, ad2, h2, b2, out + A2_OFF, out, nullptr, nullptr);
}

// round 10
// speedup vs baseline: 1.2277x; 1.1934x over previous
#include <cuda_runtime.h>
#include <cuda_bf16.h>
#include <cuda_fp16.h>
#include <math.h>
#include <stdint.h>

#define N_NODES 20000
#define N_EDGES 320000
#define NE_TOT  (N_EDGES + N_NODES)   /* 340000 incl self loops */
#define IN_CH   512
#define HID     128
#define HEADS   4
#define OUT_CH  256
#define L1_F    (HEADS * HID)         /* 512 */

#define A1_OFF  (N_NODES * OUT_CH)            /* 5,120,000 */
#define A2_OFF  (A1_OFF + NE_TOT * HEADS)     /* 6,480,000 */

/* ------------------------- scratch (device globals) ------------------------- */
__device__ float         g_h1[(size_t)N_NODES * L1_F];
__device__ __half        g_h1f[(size_t)N_NODES * L1_F];   /* fp16 copy for gather */
__device__ float         g_h2[(size_t)N_NODES * OUT_CH];
__device__ __nv_bfloat16 g_xhi[(size_t)N_NODES * IN_CH];
__device__ __nv_bfloat16 g_xlo[(size_t)N_NODES * IN_CH];
__device__ __nv_bfloat16 g_w1hi[L1_F * IN_CH];      /* transposed [N][K] */
__device__ __nv_bfloat16 g_w1lo[L1_F * IN_CH];
__device__ __nv_bfloat16 g_w2hi[OUT_CH * L1_F];
__device__ __nv_bfloat16 g_w2lo[OUT_CH * L1_F];
__device__ __nv_bfloat16 g_a1hi[(size_t)N_NODES * L1_F];
__device__ __nv_bfloat16 g_a1lo[(size_t)N_NODES * L1_F];
__device__ float g_as1[N_NODES * HEADS];
__device__ float g_ad1[N_NODES * HEADS];
__device__ float g_as2[N_NODES];
__device__ float g_ad2[N_NODES];
__device__ float g_vbuf[(size_t)NE_TOT * HEADS];    /* [head][csr_pos] */
__device__ int   g_counts[N_NODES];
__device__ int   g_cursor[N_NODES];
__device__ int   g_rowptr[N_NODES + 1];
__device__ int   g_esrc[NE_TOT];
__device__ int   g_eorig[NE_TOT];

/* ------------------------- helpers ------------------------- */
__device__ __forceinline__ uint32_t smem_u32(const void* p) {
    uint32_t a;
    asm("{ .reg .u64 t; cvta.to.shared.u64 t, %1; cvt.u32.u64 %0, t; }" : "=r"(a) : "l"(p));
    return a;
}
__device__ __forceinline__ void ldsm_x4(uint32_t& r0, uint32_t& r1, uint32_t& r2,
                                        uint32_t& r3, uint32_t addr) {
    asm volatile("ldmatrix.sync.aligned.m8n8.x4.shared.b16 {%0,%1,%2,%3}, [%4];"
                 : "=r"(r0), "=r"(r1), "=r"(r2), "=r"(r3) : "r"(addr));
}
__device__ __forceinline__ void mma_bf16(float* d, const uint32_t* a, const uint32_t* b) {
    asm volatile("mma.sync.aligned.m16n8k16.row.col.f32.bf16.bf16.f32 "
                 "{%0,%1,%2,%3}, {%4,%5,%6,%7}, {%8,%9}, {%0,%1,%2,%3};"
                 : "+f"(d[0]), "+f"(d[1]), "+f"(d[2]), "+f"(d[3])
                 : "r"(a[0]), "r"(a[1]), "r"(a[2]), "r"(a[3]), "r"(b[0]), "r"(b[1]));
}
__device__ __forceinline__ void cpa16(uint32_t dst, const void* src) {
    asm volatile("cp.async.cg.shared.global [%0], [%1], 16;" :: "r"(dst), "l"(src));
}
#define CP_COMMIT() asm volatile("cp.async.commit_group;" ::: "memory")
#define CP_WAIT0()  asm volatile("cp.async.wait_group 0;" ::: "memory")

/* ------------------------- CSR construction ------------------------- */
__device__ __forceinline__ void edge_nodes(const int* __restrict__ ei, int e,
                                           int& src, int& dst) {
    if (e < N_EDGES) { src = ei[e]; dst = ei[N_EDGES + e]; }
    else             { src = dst = e - N_EDGES; }
}

__global__ void zero_counts() {
    int i = blockIdx.x * blockDim.x + threadIdx.x;
    if (i < N_NODES) { g_counts[i] = 0; g_cursor[i] = 0; }
}

__global__ void count_deg(const int* __restrict__ ei) {
    int e = blockIdx.x * blockDim.x + threadIdx.x;
    if (e >= NE_TOT) return;
    int src, dst;
    edge_nodes(ei, e, src, dst);
    atomicAdd(&g_counts[dst], 1);
}

__global__ void scan_rowptr() {
    __shared__ int wsum[32];
    __shared__ int s_carry;
    int tid = threadIdx.x, lane = tid & 31, wid = tid >> 5;
    if (tid == 0) { g_rowptr[0] = 0; s_carry = 0; }
    __syncthreads();
    for (int base = 0; base < N_NODES; base += 1024) {
        int i = base + tid;
        int v = (i < N_NODES) ? g_counts[i] : 0;
        int x = v;
#pragma unroll
        for (int o = 1; o < 32; o <<= 1) {
            int t = __shfl_up_sync(0xFFFFFFFFu, x, o);
            if (lane >= o) x += t;
        }
        if (lane == 31) wsum[wid] = x;
        __syncthreads();
        if (wid == 0) {
            int s = wsum[lane];
#pragma unroll
            for (int o = 1; o < 32; o <<= 1) {
                int t = __shfl_up_sync(0xFFFFFFFFu, s, o);
                if (lane >= o) s += t;
            }
            wsum[lane] = s;
        }
        __syncthreads();
        int inc = x + (wid > 0 ? wsum[wid - 1] : 0) + s_carry;
        if (i < N_NODES) g_rowptr[i + 1] = inc;
        __syncthreads();
        if (tid == 1023) s_carry = inc;
        __syncthreads();
    }
}

__global__ void scatter_edges(const int* __restrict__ ei) {
    int e = blockIdx.x * blockDim.x + threadIdx.x;
    if (e >= NE_TOT) return;
    int src, dst;
    edge_nodes(ei, e, src, dst);
    int pos = g_rowptr[dst] + atomicAdd(&g_cursor[dst], 1);
    g_esrc[pos]  = src;
    g_eorig[pos] = e;
}

/* ------------------------- fp32 -> bf16 hi/lo splits ------------------------- */
__global__ void split_fp32(const float* __restrict__ in,
                           __nv_bfloat16* __restrict__ hi,
                           __nv_bfloat16* __restrict__ lo, int n) {
    int i = blockIdx.x * blockDim.x + threadIdx.x;
    if (i >= n) return;
    float v = in[i];
    __nv_bfloat16 h = __float2bfloat16(v);
    hi[i] = h;
    lo[i] = __float2bfloat16(v - __bfloat162float(h));
}

/* W [K][N] -> out [N][K] bf16 hi/lo */
__global__ void split_w_t(const float* __restrict__ W,
                          __nv_bfloat16* __restrict__ thi,
                          __nv_bfloat16* __restrict__ tlo, int K, int N) {
    int i = blockIdx.x * blockDim.x + threadIdx.x;
    if (i >= K * N) return;
    int k = i / N, n = i % N;
    float v = W[i];
    __nv_bfloat16 h = __float2bfloat16(v);
    thi[n * K + k] = h;
    tlo[n * K + k] = __float2bfloat16(v - __bfloat162float(h));
}

/* ------------------------- HMMA bf16-split GEMM (R5 config) ----------------
   C[M,N] fp32 ≈ Ahi*Bhi^T + Alo*Bhi^T + Ahi*Blo^T; A [M,K], B [N,K] bf16.
   K=512. CTA tile 128x128, 8 warps, 2-buffer cp.async, wait0.
   Optionally also writes an fp16 copy of C (for the gather kernel). */
#define KSTAGES (512 / 16)    /* 32 */
#define SROW    24

__global__ __launch_bounds__(256)
void gemm_hmma(const __nv_bfloat16* __restrict__ Ahi, const __nv_bfloat16* __restrict__ Alo,
               const __nv_bfloat16* __restrict__ Bhi, const __nv_bfloat16* __restrict__ Blo,
               float* __restrict__ C, __half* __restrict__ Cf, int M, int N) {
    __shared__ __align__(16) __nv_bfloat16 sA[2][2][128][SROW]; /* [buf][hi/lo] */
    __shared__ __align__(16) __nv_bfloat16 sB[2][2][128][SROW];

    int tid = threadIdx.x, wid = tid >> 5, lane = tid & 31;
    int m0 = blockIdx.y * 128, n0 = blockIdx.x * 128;
    int wm = (wid >> 1) * 32;
    int wn = (wid & 1) * 64;

    int prow = tid >> 1, pseg = tid & 1;
    int agr = m0 + prow; if (agr >= M) agr = M - 1;
    const __nv_bfloat16* pAhi = Ahi + (size_t)agr * 512 + pseg * 8;
    const __nv_bfloat16* pAlo = Alo + (size_t)agr * 512 + pseg * 8;
    const __nv_bfloat16* pBhi = Bhi + (size_t)(n0 + prow) * 512 + pseg * 8;
    const __nv_bfloat16* pBlo = Blo + (size_t)(n0 + prow) * 512 + pseg * 8;
    uint32_t dA0[2], dA1[2], dB0[2], dB1[2];
#pragma unroll
    for (int b = 0; b < 2; b++) {
        dA0[b] = smem_u32(&sA[b][0][prow][pseg * 8]);
        dA1[b] = smem_u32(&sA[b][1][prow][pseg * 8]);
        dB0[b] = smem_u32(&sB[b][0][prow][pseg * 8]);
        dB1[b] = smem_u32(&sB[b][1][prow][pseg * 8]);
    }

    int a_row = (lane & 15), a_k = (lane >> 4) * 8;
    int b_nrow = ((lane >> 4) << 3) + (lane & 7), b_k = ((lane >> 3) & 1) * 8;
    uint32_t a_base0 = smem_u32(&sA[0][0][wm + a_row][a_k]);
    uint32_t a_base1 = smem_u32(&sA[0][1][wm + a_row][a_k]);
    uint32_t b_base0 = smem_u32(&sB[0][0][wn + b_nrow][b_k]);
    uint32_t b_base1 = smem_u32(&sB[0][1][wn + b_nrow][b_k]);
    const uint32_t BUFSTRIDE = 2 * 128 * SROW * 2;

    float acc[2][8][4];
#pragma unroll
    for (int i = 0; i < 2; i++)
#pragma unroll
        for (int j = 0; j < 8; j++)
#pragma unroll
            for (int q = 0; q < 4; q++) acc[i][j][q] = 0.f;

    cpa16(dA0[0], pAhi);
    cpa16(dA1[0], pAlo);
    cpa16(dB0[0], pBhi);
    cpa16(dB1[0], pBlo);
    CP_COMMIT();
    CP_WAIT0();
    __syncthreads();

    for (int t = 0; t < KSTAGES; t++) {
        int buf = t & 1;
        if (t + 1 < KSTAGES) {
            int nb = (t + 1) & 1, ko = (t + 1) * 16;
            cpa16(dA0[nb], pAhi + ko);
            cpa16(dA1[nb], pAlo + ko);
            cpa16(dB0[nb], pBhi + ko);
            cpa16(dB1[nb], pBlo + ko);
            CP_COMMIT();
        }

        uint32_t abase = buf * BUFSTRIDE;
        uint32_t ahi[2][4], alo[2][4];
#pragma unroll
        for (int ma = 0; ma < 2; ma++) {
            ldsm_x4(ahi[ma][0], ahi[ma][1], ahi[ma][2], ahi[ma][3],
                    a_base0 + abase + ma * 16 * SROW * 2);
            ldsm_x4(alo[ma][0], alo[ma][1], alo[ma][2], alo[ma][3],
                    a_base1 + abase + ma * 16 * SROW * 2);
        }
        uint32_t bhi[4][4], blo[4][4];
#pragma unroll
        for (int g = 0; g < 4; g++) {
            ldsm_x4(bhi[g][0], bhi[g][1], bhi[g][2], bhi[g][3],
                    b_base0 + abase + g * 16 * SROW * 2);
            ldsm_x4(blo[g][0], blo[g][1], blo[g][2], blo[g][3],
                    b_base1 + abase + g * 16 * SROW * 2);
        }

#pragma unroll
        for (int ma = 0; ma < 2; ma++)
#pragma unroll
            for (int g = 0; g < 4; g++)
#pragma unroll
                for (int h = 0; h < 2; h++) {
                    float* d = acc[ma][g * 2 + h];
                    mma_bf16(d, ahi[ma], &bhi[g][h * 2]);
                    mma_bf16(d, alo[ma], &bhi[g][h * 2]);
                    mma_bf16(d, ahi[ma], &blo[g][h * 2]);
                }

        CP_WAIT0();
        __syncthreads();
    }

    /* epilogue: fp32 C (+ optional fp16 copy) */
    int lg = lane >> 2, lt = lane & 3;
#pragma unroll
    for (int ma = 0; ma < 2; ma++) {
        int mrow0 = m0 + wm + ma * 16 + lg;
#pragma unroll
        for (int nb = 0; nb < 8; nb++) {
            int n = n0 + wn + nb * 8 + lt * 2;
            float* d = acc[ma][nb];
            if (mrow0 < M) {
                *(float2*)(C + (size_t)mrow0 * N + n) = make_float2(d[0], d[1]);
                if (Cf) *(__half2*)(Cf + (size_t)mrow0 * N + n) =
                    __floats2half2_rn(d[0], d[1]);
            }
            if (mrow0 + 8 < M) {
                *(float2*)(C + (size_t)(mrow0 + 8) * N + n) = make_float2(d[2], d[3]);
                if (Cf) *(__half2*)(Cf + (size_t)(mrow0 + 8) * N + n) =
                    __floats2half2_rn(d[2], d[3]);
            }
        }
    }
}

/* ------------------------- attention coefficients ------------------------- */
template <int H, int C>
__global__ void attn_coef(const float* __restrict__ h,
                          const float* __restrict__ a_src,
                          const float* __restrict__ a_dst,
                          float* __restrict__ as, float* __restrict__ ad) {
    int gw = (blockIdx.x * blockDim.x + threadIdx.x) >> 5;
    int lane = threadIdx.x & 31;
    if (gw >= N_NODES * H) return;
    int n = gw / H, hh = gw % H;
    const float* hp = h + (size_t)n * (H * C) + hh * C;
    const float* sp = a_src + hh * C;
    const float* dp = a_dst + hh * C;
    float s = 0.f, d = 0.f;
#pragma unroll
    for (int c = lane; c < C; c += 32) {
        float v = hp[c];
        s += v * sp[c];
        d += v * dp[c];
    }
#pragma unroll
    for (int o = 16; o; o >>= 1) {
        s += __shfl_xor_sync(0xFFFFFFFFu, s, o);
        d += __shfl_xor_sync(0xFFFFFFFFu, d, o);
    }
    if (lane == 0) { as[gw] = s; ad[gw] = d; }
}

/* ------------------------- fused softmax + aggregate -------------------------
   GH: gather features from fp16 copy (halves L2 gather traffic). */
template <int H, int C, bool ELU, bool SPLIT, bool GH>
__global__ __launch_bounds__(256)
void fused_agg(const float* __restrict__ as, const float* __restrict__ ad,
               const float* __restrict__ hfeat, const __half* __restrict__ hfeat_h,
               const float* __restrict__ bias,
               float* __restrict__ alpha_out, float* __restrict__ aggout,
               __nv_bfloat16* __restrict__ ohi, __nv_bfloat16* __restrict__ olo) {
    int gw = (blockIdx.x * blockDim.x + threadIdx.x) >> 5;
    int lane = threadIdx.x & 31;
    if (gw >= N_NODES * H) return;
    int dst = gw / H, hh = gw % H;

    int beg = g_rowptr[dst], end = g_rowptr[dst + 1];
    float adv = ad[dst * H + hh];
    float* vb = g_vbuf + (size_t)hh * NE_TOT;

    /* pass 1: gather logits once, store contiguously, track max */
    float mx = -1e30f;
    for (int i = beg + lane; i < end; i += 32) {
        float v = as[g_esrc[i] * H + hh] + adv;
        v = v > 0.f ? v : 0.2f * v;
        vb[i] = v;
        mx = fmaxf(mx, v);
    }
#pragma unroll
    for (int o = 16; o; o >>= 1) mx = fmaxf(mx, __shfl_xor_sync(0xFFFFFFFFu, mx, o));

    /* pass 2: denom */
    float sm = 0.f;
    for (int i = beg + lane; i < end; i += 32) sm += __expf(vb[i] - mx);
#pragma unroll
    for (int o = 16; o; o >>= 1) sm += __shfl_xor_sync(0xFFFFFFFFu, sm, o);
    float inv = 1.f / sm;

    /* pass 3: alpha + gather-accumulate (software pipelined, depth 2) */
    constexpr int R = C / 128;
    float4 acc[R];
#pragma unroll
    for (int r = 0; r < R; r++) acc[r] = make_float4(0.f, 0.f, 0.f, 0.f);

    auto load_feats = [&](int s, float4* t) {
        if (GH) {
            const uint2* hp = (const uint2*)(hfeat_h + (size_t)s * (H * C) + hh * C);
#pragma unroll
            for (int r = 0; r < R; r++) {
                uint2 u = hp[lane + 32 * r];
                float2 f01 = __half22float2(*(__half2*)&u.x);
                float2 f23 = __half22float2(*(__half2*)&u.y);
                t[r] = make_float4(f01.x, f01.y, f23.x, f23.y);
            }
        } else {
            const float4* hp = (const float4*)(hfeat + (size_t)s * (H * C) + hh * C);
#pragma unroll
            for (int r = 0; r < R; r++) t[r] = hp[lane + 32 * r];
        }
    };

    int i = beg;
    int eo = g_eorig[i];
    float vv = vb[i];
    float4 tv[R];
    load_feats(g_esrc[i], tv);
    for (;;) {
        int inext = i + 1;
        bool more = inext < end;
        int eo2 = 0;
        float vv2 = 0.f;
        float4 tv2[R];
        if (more) {
            eo2 = g_eorig[inext];
            vv2 = vb[inext];
            load_feats(g_esrc[inext], tv2);
        }
        float a = __expf(vv - mx) * inv;
        if (lane == 0) alpha_out[eo * H + hh] = a;
#pragma unroll
        for (int r = 0; r < R; r++) {
            acc[r].x += a * tv[r].x;
            acc[r].y += a * tv[r].y;
            acc[r].z += a * tv[r].z;
            acc[r].w += a * tv[r].w;
        }
        if (!more) break;
        eo = eo2; vv = vv2;
#pragma unroll
        for (int r = 0; r < R; r++) tv[r] = tv2[r];
        i = inext;
    }

    /* epilogue: bias (+ELU), fp32 out or bf16 hi/lo split */
#pragma unroll
    for (int r = 0; r < R; r++) {
        int c = (lane + 32 * r) * 4;
        const float* bp = bias + hh * C + c;
        float4 o = acc[r];
        o.x += bp[0]; o.y += bp[1]; o.z += bp[2]; o.w += bp[3];
        if (ELU) {
            o.x = o.x > 0.f ? o.x : expm1f(o.x);
            o.y = o.y > 0.f ? o.y : expm1f(o.y);
            o.z = o.z > 0.f ? o.z : expm1f(o.z);
            o.w = o.w > 0.f ? o.w : expm1f(o.w);
        }
        if (SPLIT) {
            size_t base = (size_t)dst * (H * C) + hh * C + c;
            float vv4[4] = { o.x, o.y, o.z, o.w };
#pragma unroll
            for (int q = 0; q < 4; q++) {
                __nv_bfloat16 h = __float2bfloat16(vv4[q]);
                ohi[base + q] = h;
                olo[base + q] = __float2bfloat16(vv4[q] - __bfloat162float(h));
            }
        } else {
            float* op = aggout + (size_t)dst * (H * C) + hh * C;
            ((float4*)op)[lane + 32 * r] = o;
        }
    }
}

/* ------------------------- launch ------------------------- */
extern "C" void kernel_launch(void* const* d_in, const int* in_sizes, int n_in,
                              void* d_out, int out_size) {
    const float* x      = (const float*)d_in[0];
    const int*   ei     = (const int*)  d_in[1];
    const float* W1     = (const float*)d_in[2];
    const float* a_src1 = (const float*)d_in[3];
    const float* a_dst1 = (const float*)d_in[4];
    const float* b1     = (const float*)d_in[5];
    const float* W2     = (const float*)d_in[6];
    const float* a_src2 = (const float*)d_in[7];
    const float* a_dst2 = (const float*)d_in[8];
    const float* b2     = (const float*)d_in[9];
    float* out = (float*)d_out;

    float *h1, *h2, *as1, *ad1, *as2, *ad2;
    __half* h1f;
    __nv_bfloat16 *xhi, *xlo, *w1hi, *w1lo, *w2hi, *w2lo, *a1hi, *a1lo;
    cudaGetSymbolAddress((void**)&h1,   g_h1);
    cudaGetSymbolAddress((void**)&h1f,  g_h1f);
    cudaGetSymbolAddress((void**)&h2,   g_h2);
    cudaGetSymbolAddress((void**)&as1,  g_as1);
    cudaGetSymbolAddress((void**)&ad1,  g_ad1);
    cudaGetSymbolAddress((void**)&as2,  g_as2);
    cudaGetSymbolAddress((void**)&ad2,  g_ad2);
    cudaGetSymbolAddress((void**)&xhi,  g_xhi);
    cudaGetSymbolAddress((void**)&xlo,  g_xlo);
    cudaGetSymbolAddress((void**)&w1hi, g_w1hi);
    cudaGetSymbolAddress((void**)&w1lo, g_w1lo);
    cudaGetSymbolAddress((void**)&w2hi, g_w2hi);
    cudaGetSymbolAddress((void**)&w2lo, g_w2lo);
    cudaGetSymbolAddress((void**)&a1hi, g_a1hi);
    cudaGetSymbolAddress((void**)&a1lo, g_a1lo);

    /* second stream + fork/join events (created once, before first capture) */
    static cudaStream_t s2 = nullptr;
    static cudaEvent_t evF = nullptr, evJ = nullptr;
    if (!s2) {
        cudaStreamCreateWithFlags(&s2, cudaStreamNonBlocking);
        cudaEventCreateWithFlags(&evF, cudaEventDisableTiming);
        cudaEventCreateWithFlags(&evJ, cudaEventDisableTiming);
    }

    /* fork: CSR build runs concurrently with splits + gemm1 */
    cudaEventRecord(evF, 0);
    cudaStreamWaitEvent(s2, evF, 0);
    zero_counts<<<(N_NODES + 255) / 256, 256, 0, s2>>>();
    count_deg<<<(NE_TOT + 255) / 256, 256, 0, s2>>>(ei);
    scan_rowptr<<<1, 1024, 0, s2>>>();
    scatter_edges<<<(NE_TOT + 255) / 256, 256, 0, s2>>>(ei);
    cudaEventRecord(evJ, s2);

    /* main stream: conversions, gemm1, attn1 */
    split_fp32<<<(N_NODES * IN_CH + 255) / 256, 256>>>(x, xhi, xlo, N_NODES * IN_CH);
    split_w_t<<<(IN_CH * L1_F + 255) / 256, 256>>>(W1, w1hi, w1lo, IN_CH, L1_F);
    split_w_t<<<(L1_F * OUT_CH + 255) / 256, 256>>>(W2, w2hi, w2lo, L1_F, OUT_CH);
    gemm_hmma<<<dim3(L1_F / 128, 157), 256>>>(xhi, xlo, w1hi, w1lo, h1, h1f, N_NODES, L1_F);
    attn_coef<HEADS, HID><<<(N_NODES * HEADS + 7) / 8, 256>>>(h1, a_src1, a_dst1, as1, ad1);

    /* join: need CSR for aggregation */
    cudaStreamWaitEvent(0, evJ, 0);
    fused_agg<HEADS, HID, true, true, true><<<(N_NODES * HEADS + 7) / 8, 256>>>(
        as1, ad1, h1, h1f, b1, out + A1_OFF, nullptr, a1hi, a1lo);

    /* layer 2 (fp32 gather) */
    gemm_hmma<<<dim3(OUT_CH / 128, 157), 256>>>(a1hi, a1lo, w2hi, w2lo, h2, (__half*)nullptr,
                                                N_NODES, OUT_CH);
    attn_coef<1, OUT_CH><<<(N_NODES + 7) / 8, 256>>>(h2, a_src2, a_dst2, as2, ad2);
    fused_agg<1, OUT_CH, false, false, false><<<(N_NODES + 7) / 8, 256>>>(
        as2, ad2, h2, (const __half*)nullptr, b2, out + A2_OFF, out, nullptr, nullptr);
}

// round 11
// speedup vs baseline: 1.2807x; 1.0432x over previous
#include <cuda_runtime.h>
#include <cuda_bf16.h>
#include <cuda_fp16.h>
#include <math.h>
#include <stdint.h>

#define N_NODES 20000
#define N_EDGES 320000
#define NE_TOT  (N_EDGES + N_NODES)   /* 340000 incl self loops */
#define IN_CH   512
#define HID     128
#define HEADS   4
#define OUT_CH  256
#define L1_F    (HEADS * HID)         /* 512 */

#define A1_OFF  (N_NODES * OUT_CH)            /* 5,120,000 */
#define A2_OFF  (A1_OFF + NE_TOT * HEADS)     /* 6,480,000 */

/* ------------------------- scratch (device globals) ------------------------- */
__device__ __half        g_h1f[(size_t)N_NODES * L1_F];   /* h1, fp16 */
__device__ __half        g_h2f[(size_t)N_NODES * OUT_CH]; /* h2, fp16 */
__device__ __nv_bfloat16 g_xhi[(size_t)N_NODES * IN_CH];
__device__ __nv_bfloat16 g_xlo[(size_t)N_NODES * IN_CH];
__device__ __nv_bfloat16 g_w1hi[L1_F * IN_CH];      /* transposed [N][K] */
__device__ __nv_bfloat16 g_w1lo[L1_F * IN_CH];
__device__ __nv_bfloat16 g_w2hi[OUT_CH * L1_F];
__device__ __nv_bfloat16 g_w2lo[OUT_CH * L1_F];
__device__ __nv_bfloat16 g_a1hi[(size_t)N_NODES * L1_F];
__device__ __nv_bfloat16 g_a1lo[(size_t)N_NODES * L1_F];
__device__ float g_as1[N_NODES * HEADS];
__device__ float g_ad1[N_NODES * HEADS];
__device__ float g_as2[N_NODES];
__device__ float g_ad2[N_NODES];
__device__ float g_vbuf[(size_t)NE_TOT * HEADS];    /* [head][csr_pos] */
__device__ int   g_counts[N_NODES];
__device__ int   g_cursor[N_NODES];
__device__ int   g_rowptr[N_NODES + 1];
__device__ int   g_esrc[NE_TOT];
__device__ int   g_eorig[NE_TOT];

/* ------------------------- helpers ------------------------- */
__device__ __forceinline__ uint32_t smem_u32(const void* p) {
    uint32_t a;
    asm("{ .reg .u64 t; cvta.to.shared.u64 t, %1; cvt.u32.u64 %0, t; }" : "=r"(a) : "l"(p));
    return a;
}
__device__ __forceinline__ void ldsm_x4(uint32_t& r0, uint32_t& r1, uint32_t& r2,
                                        uint32_t& r3, uint32_t addr) {
    asm volatile("ldmatrix.sync.aligned.m8n8.x4.shared.b16 {%0,%1,%2,%3}, [%4];"
                 : "=r"(r0), "=r"(r1), "=r"(r2), "=r"(r3) : "r"(addr));
}
__device__ __forceinline__ void mma_bf16(float* d, const uint32_t* a, const uint32_t* b) {
    asm volatile("mma.sync.aligned.m16n8k16.row.col.f32.bf16.bf16.f32 "
                 "{%0,%1,%2,%3}, {%4,%5,%6,%7}, {%8,%9}, {%0,%1,%2,%3};"
                 : "+f"(d[0]), "+f"(d[1]), "+f"(d[2]), "+f"(d[3])
                 : "r"(a[0]), "r"(a[1]), "r"(a[2]), "r"(a[3]), "r"(b[0]), "r"(b[1]));
}
__device__ __forceinline__ void cpa16(uint32_t dst, const void* src) {
    asm volatile("cp.async.cg.shared.global [%0], [%1], 16;" :: "r"(dst), "l"(src));
}
#define CP_COMMIT() asm volatile("cp.async.commit_group;" ::: "memory")
#define CP_WAIT0()  asm volatile("cp.async.wait_group 0;" ::: "memory")

/* ------------------------- CSR construction ------------------------- */
__device__ __forceinline__ void edge_nodes(const int* __restrict__ ei, int e,
                                           int& src, int& dst) {
    if (e < N_EDGES) { src = ei[e]; dst = ei[N_EDGES + e]; }
    else             { src = dst = e - N_EDGES; }
}

__global__ void zero_counts() {
    int i = blockIdx.x * blockDim.x + threadIdx.x;
    if (i < N_NODES) { g_counts[i] = 0; g_cursor[i] = 0; }
}

__global__ void count_deg(const int* __restrict__ ei) {
    int e = blockIdx.x * blockDim.x + threadIdx.x;
    if (e >= NE_TOT) return;
    int src, dst;
    edge_nodes(ei, e, src, dst);
    atomicAdd(&g_counts[dst], 1);
}

__global__ void scan_rowptr() {
    __shared__ int wsum[32];
    __shared__ int s_carry;
    int tid = threadIdx.x, lane = tid & 31, wid = tid >> 5;
    if (tid == 0) { g_rowptr[0] = 0; s_carry = 0; }
    __syncthreads();
    for (int base = 0; base < N_NODES; base += 1024) {
        int i = base + tid;
        int v = (i < N_NODES) ? g_counts[i] : 0;
        int x = v;
#pragma unroll
        for (int o = 1; o < 32; o <<= 1) {
            int t = __shfl_up_sync(0xFFFFFFFFu, x, o);
            if (lane >= o) x += t;
        }
        if (lane == 31) wsum[wid] = x;
        __syncthreads();
        if (wid == 0) {
            int s = wsum[lane];
#pragma unroll
            for (int o = 1; o < 32; o <<= 1) {
                int t = __shfl_up_sync(0xFFFFFFFFu, s, o);
                if (lane >= o) s += t;
            }
            wsum[lane] = s;
        }
        __syncthreads();
        int inc = x + (wid > 0 ? wsum[wid - 1] : 0) + s_carry;
        if (i < N_NODES) g_rowptr[i + 1] = inc;
        __syncthreads();
        if (tid == 1023) s_carry = inc;
        __syncthreads();
    }
}

__global__ void scatter_edges(const int* __restrict__ ei) {
    int e = blockIdx.x * blockDim.x + threadIdx.x;
    if (e >= NE_TOT) return;
    int src, dst;
    edge_nodes(ei, e, src, dst);
    int pos = g_rowptr[dst] + atomicAdd(&g_cursor[dst], 1);
    g_esrc[pos]  = src;
    g_eorig[pos] = e;
}

/* ------------------------- fp32 -> bf16 hi/lo splits ------------------------- */
__global__ void split_fp32(const float* __restrict__ in,
                           __nv_bfloat16* __restrict__ hi,
                           __nv_bfloat16* __restrict__ lo, int n) {
    int i = blockIdx.x * blockDim.x + threadIdx.x;
    if (i >= n) return;
    float v = in[i];
    __nv_bfloat16 h = __float2bfloat16(v);
    hi[i] = h;
    lo[i] = __float2bfloat16(v - __bfloat162float(h));
}

/* W [K][N] -> out [N][K] bf16 hi/lo */
__global__ void split_w_t(const float* __restrict__ W,
                          __nv_bfloat16* __restrict__ thi,
                          __nv_bfloat16* __restrict__ tlo, int K, int N) {
    int i = blockIdx.x * blockDim.x + threadIdx.x;
    if (i >= K * N) return;
    int k = i / N, n = i % N;
    float v = W[i];
    __nv_bfloat16 h = __float2bfloat16(v);
    thi[n * K + k] = h;
    tlo[n * K + k] = __float2bfloat16(v - __bfloat162float(h));
}

/* ------------------------- HMMA bf16-split GEMM (R5 config) ----------------
   C[M,N] ≈ Ahi*Bhi^T + Alo*Bhi^T + Ahi*Blo^T; output written as fp16 ONLY. */
#define KSTAGES (512 / 16)    /* 32 */
#define SROW    24

__global__ __launch_bounds__(256)
void gemm_hmma(const __nv_bfloat16* __restrict__ Ahi, const __nv_bfloat16* __restrict__ Alo,
               const __nv_bfloat16* __restrict__ Bhi, const __nv_bfloat16* __restrict__ Blo,
               __half* __restrict__ Cf, int M, int N) {
    __shared__ __align__(16) __nv_bfloat16 sA[2][2][128][SROW]; /* [buf][hi/lo] */
    __shared__ __align__(16) __nv_bfloat16 sB[2][2][128][SROW];

    int tid = threadIdx.x, wid = tid >> 5, lane = tid & 31;
    int m0 = blockIdx.y * 128, n0 = blockIdx.x * 128;
    int wm = (wid >> 1) * 32;
    int wn = (wid & 1) * 64;

    int prow = tid >> 1, pseg = tid & 1;
    int agr = m0 + prow; if (agr >= M) agr = M - 1;
    const __nv_bfloat16* pAhi = Ahi + (size_t)agr * 512 + pseg * 8;
    const __nv_bfloat16* pAlo = Alo + (size_t)agr * 512 + pseg * 8;
    const __nv_bfloat16* pBhi = Bhi + (size_t)(n0 + prow) * 512 + pseg * 8;
    const __nv_bfloat16* pBlo = Blo + (size_t)(n0 + prow) * 512 + pseg * 8;
    uint32_t dA0[2], dA1[2], dB0[2], dB1[2];
#pragma unroll
    for (int b = 0; b < 2; b++) {
        dA0[b] = smem_u32(&sA[b][0][prow][pseg * 8]);
        dA1[b] = smem_u32(&sA[b][1][prow][pseg * 8]);
        dB0[b] = smem_u32(&sB[b][0][prow][pseg * 8]);
        dB1[b] = smem_u32(&sB[b][1][prow][pseg * 8]);
    }

    int a_row = (lane & 15), a_k = (lane >> 4) * 8;
    int b_nrow = ((lane >> 4) << 3) + (lane & 7), b_k = ((lane >> 3) & 1) * 8;
    uint32_t a_base0 = smem_u32(&sA[0][0][wm + a_row][a_k]);
    uint32_t a_base1 = smem_u32(&sA[0][1][wm + a_row][a_k]);
    uint32_t b_base0 = smem_u32(&sB[0][0][wn + b_nrow][b_k]);
    uint32_t b_base1 = smem_u32(&sB[0][1][wn + b_nrow][b_k]);
    const uint32_t BUFSTRIDE = 2 * 128 * SROW * 2;

    float acc[2][8][4];
#pragma unroll
    for (int i = 0; i < 2; i++)
#pragma unroll
        for (int j = 0; j < 8; j++)
#pragma unroll
            for (int q = 0; q < 4; q++) acc[i][j][q] = 0.f;

    cpa16(dA0[0], pAhi);
    cpa16(dA1[0], pAlo);
    cpa16(dB0[0], pBhi);
    cpa16(dB1[0], pBlo);
    CP_COMMIT();
    CP_WAIT0();
    __syncthreads();

    for (int t = 0; t < KSTAGES; t++) {
        int buf = t & 1;
        if (t + 1 < KSTAGES) {
            int nb = (t + 1) & 1, ko = (t + 1) * 16;
            cpa16(dA0[nb], pAhi + ko);
            cpa16(dA1[nb], pAlo + ko);
            cpa16(dB0[nb], pBhi + ko);
            cpa16(dB1[nb], pBlo + ko);
            CP_COMMIT();
        }

        uint32_t abase = buf * BUFSTRIDE;
        uint32_t ahi[2][4], alo[2][4];
#pragma unroll
        for (int ma = 0; ma < 2; ma++) {
            ldsm_x4(ahi[ma][0], ahi[ma][1], ahi[ma][2], ahi[ma][3],
                    a_base0 + abase + ma * 16 * SROW * 2);
            ldsm_x4(alo[ma][0], alo[ma][1], alo[ma][2], alo[ma][3],
                    a_base1 + abase + ma * 16 * SROW * 2);
        }
        uint32_t bhi[4][4], blo[4][4];
#pragma unroll
        for (int g = 0; g < 4; g++) {
            ldsm_x4(bhi[g][0], bhi[g][1], bhi[g][2], bhi[g][3],
                    b_base0 + abase + g * 16 * SROW * 2);
            ldsm_x4(blo[g][0], blo[g][1], blo[g][2], blo[g][3],
                    b_base1 + abase + g * 16 * SROW * 2);
        }

#pragma unroll
        for (int ma = 0; ma < 2; ma++)
#pragma unroll
            for (int g = 0; g < 4; g++)
#pragma unroll
                for (int h = 0; h < 2; h++) {
                    float* d = acc[ma][g * 2 + h];
                    mma_bf16(d, ahi[ma], &bhi[g][h * 2]);
                    mma_bf16(d, alo[ma], &bhi[g][h * 2]);
                    mma_bf16(d, ahi[ma], &blo[g][h * 2]);
                }

        CP_WAIT0();
        __syncthreads();
    }

    /* epilogue: fp16 C only */
    int lg = lane >> 2, lt = lane & 3;
#pragma unroll
    for (int ma = 0; ma < 2; ma++) {
        int mrow0 = m0 + wm + ma * 16 + lg;
#pragma unroll
        for (int nb = 0; nb < 8; nb++) {
            int n = n0 + wn + nb * 8 + lt * 2;
            float* d = acc[ma][nb];
            if (mrow0 < M)
                *(__half2*)(Cf + (size_t)mrow0 * N + n) = __floats2half2_rn(d[0], d[1]);
            if (mrow0 + 8 < M)
                *(__half2*)(Cf + (size_t)(mrow0 + 8) * N + n) = __floats2half2_rn(d[2], d[3]);
        }
    }
}

/* ------------------------- attention coefficients (fp16 h) ----------------- */
template <int H, int C>
__global__ void attn_coef(const __half* __restrict__ h,
                          const float* __restrict__ a_src,
                          const float* __restrict__ a_dst,
                          float* __restrict__ as, float* __restrict__ ad) {
    int gw = (blockIdx.x * blockDim.x + threadIdx.x) >> 5;
    int lane = threadIdx.x & 31;
    if (gw >= N_NODES * H) return;
    int n = gw / H, hh = gw % H;
    const __half2* hp = (const __half2*)(h + (size_t)n * (H * C) + hh * C);
    const float* sp = a_src + hh * C;
    const float* dp = a_dst + hh * C;
    float s = 0.f, d = 0.f;
#pragma unroll
    for (int r = 0; r < C / 64; r++) {
        int c2 = lane + 32 * r;
        float2 f = __half22float2(hp[c2]);
        s += f.x * sp[c2 * 2] + f.y * sp[c2 * 2 + 1];
        d += f.x * dp[c2 * 2] + f.y * dp[c2 * 2 + 1];
    }
#pragma unroll
    for (int o = 16; o; o >>= 1) {
        s += __shfl_xor_sync(0xFFFFFFFFu, s, o);
        d += __shfl_xor_sync(0xFFFFFFFFu, d, o);
    }
    if (lane == 0) { as[gw] = s; ad[gw] = d; }
}

/* ------------------------- fused softmax + aggregate (fp16 gather) --------- */
template <int H, int C, bool ELU, bool SPLIT>
__global__ __launch_bounds__(256)
void fused_agg(const float* __restrict__ as, const float* __restrict__ ad,
               const __half* __restrict__ hfeat_h, const float* __restrict__ bias,
               float* __restrict__ alpha_out, float* __restrict__ aggout,
               __nv_bfloat16* __restrict__ ohi, __nv_bfloat16* __restrict__ olo) {
    int gw = (blockIdx.x * blockDim.x + threadIdx.x) >> 5;
    int lane = threadIdx.x & 31;
    if (gw >= N_NODES * H) return;
    int dst = gw / H, hh = gw % H;

    int beg = g_rowptr[dst], end = g_rowptr[dst + 1];
    float adv = ad[dst * H + hh];
    float* vb = g_vbuf + (size_t)hh * NE_TOT;

    /* pass 1: gather logits once, store contiguously, track max */
    float mx = -1e30f;
    for (int i = beg + lane; i < end; i += 32) {
        float v = as[g_esrc[i] * H + hh] + adv;
        v = v > 0.f ? v : 0.2f * v;
        vb[i] = v;
        mx = fmaxf(mx, v);
    }
#pragma unroll
    for (int o = 16; o; o >>= 1) mx = fmaxf(mx, __shfl_xor_sync(0xFFFFFFFFu, mx, o));

    /* pass 2: denom */
    float sm = 0.f;
    for (int i = beg + lane; i < end; i += 32) sm += __expf(vb[i] - mx);
#pragma unroll
    for (int o = 16; o; o >>= 1) sm += __shfl_xor_sync(0xFFFFFFFFu, sm, o);
    float inv = 1.f / sm;

    /* pass 3: alpha + gather-accumulate (software pipelined, depth 2) */
    constexpr int R = C / 128;
    float4 acc[R];
#pragma unroll
    for (int r = 0; r < R; r++) acc[r] = make_float4(0.f, 0.f, 0.f, 0.f);

    auto load_feats = [&](int s, float4* t) {
        const uint2* hp = (const uint2*)(hfeat_h + (size_t)s * (H * C) + hh * C);
#pragma unroll
        for (int r = 0; r < R; r++) {
            uint2 u = hp[lane + 32 * r];
            float2 f01 = __half22float2(*(__half2*)&u.x);
            float2 f23 = __half22float2(*(__half2*)&u.y);
            t[r] = make_float4(f01.x, f01.y, f23.x, f23.y);
        }
    };

    int i = beg;
    int eo = g_eorig[i];
    float vv = vb[i];
    float4 tv[R];
    load_feats(g_esrc[i], tv);
    for (;;) {
        int inext = i + 1;
        bool more = inext < end;
        int eo2 = 0;
        float vv2 = 0.f;
        float4 tv2[R];
        if (more) {
            eo2 = g_eorig[inext];
            vv2 = vb[inext];
            load_feats(g_esrc[inext], tv2);
        }
        float a = __expf(vv - mx) * inv;
        if (lane == 0) alpha_out[eo * H + hh] = a;
#pragma unroll
        for (int r = 0; r < R; r++) {
            acc[r].x += a * tv[r].x;
            acc[r].y += a * tv[r].y;
            acc[r].z += a * tv[r].z;
            acc[r].w += a * tv[r].w;
        }
        if (!more) break;
        eo = eo2; vv = vv2;
#pragma unroll
        for (int r = 0; r < R; r++) tv[r] = tv2[r];
        i = inext;
    }

    /* epilogue: bias (+ELU), fp32 out or bf16 hi/lo split */
#pragma unroll
    for (int r = 0; r < R; r++) {
        int c = (lane + 32 * r) * 4;
        const float* bp = bias + hh * C + c;
        float4 o = acc[r];
        o.x += bp[0]; o.y += bp[1]; o.z += bp[2]; o.w += bp[3];
        if (ELU) {
            o.x = o.x > 0.f ? o.x : expm1f(o.x);
            o.y = o.y > 0.f ? o.y : expm1f(o.y);
            o.z = o.z > 0.f ? o.z : expm1f(o.z);
            o.w = o.w > 0.f ? o.w : expm1f(o.w);
        }
        if (SPLIT) {
            size_t base = (size_t)dst * (H * C) + hh * C + c;
            float vv4[4] = { o.x, o.y, o.z, o.w };
#pragma unroll
            for (int q = 0; q < 4; q++) {
                __nv_bfloat16 h = __float2bfloat16(vv4[q]);
                ohi[base + q] = h;
                olo[base + q] = __float2bfloat16(vv4[q] - __bfloat162float(h));
            }
        } else {
            float* op = aggout + (size_t)dst * (H * C) + hh * C;
            ((float4*)op)[lane + 32 * r] = o;
        }
    }
}

/* ------------------------- launch ------------------------- */
extern "C" void kernel_launch(void* const* d_in, const int* in_sizes, int n_in,
                              void* d_out, int out_size) {
    const float* x      = (const float*)d_in[0];
    const int*   ei     = (const int*)  d_in[1];
    const float* W1     = (const float*)d_in[2];
    const float* a_src1 = (const float*)d_in[3];
    const float* a_dst1 = (const float*)d_in[4];
    const float* b1     = (const float*)d_in[5];
    const float* W2     = (const float*)d_in[6];
    const float* a_src2 = (const float*)d_in[7];
    const float* a_dst2 = (const float*)d_in[8];
    const float* b2     = (const float*)d_in[9];
    float* out = (float*)d_out;

    float *as1, *ad1, *as2, *ad2;
    __half *h1f, *h2f;
    __nv_bfloat16 *xhi, *xlo, *w1hi, *w1lo, *w2hi, *w2lo, *a1hi, *a1lo;
    cudaGetSymbolAddress((void**)&h1f,  g_h1f);
    cudaGetSymbolAddress((void**)&h2f,  g_h2f);
    cudaGetSymbolAddress((void**)&as1,  g_as1);
    cudaGetSymbolAddress((void**)&ad1,  g_ad1);
    cudaGetSymbolAddress((void**)&as2,  g_as2);
    cudaGetSymbolAddress((void**)&ad2,  g_ad2);
    cudaGetSymbolAddress((void**)&xhi,  g_xhi);
    cudaGetSymbolAddress((void**)&xlo,  g_xlo);
    cudaGetSymbolAddress((void**)&w1hi, g_w1hi);
    cudaGetSymbolAddress((void**)&w1lo, g_w1lo);
    cudaGetSymbolAddress((void**)&w2hi, g_w2hi);
    cudaGetSymbolAddress((void**)&w2lo, g_w2lo);
    cudaGetSymbolAddress((void**)&a1hi, g_a1hi);
    cudaGetSymbolAddress((void**)&a1lo, g_a1lo);

    /* second stream + fork/join events (created once, before first capture) */
    static cudaStream_t s2 = nullptr;
    static cudaEvent_t evF = nullptr, evJ = nullptr;
    if (!s2) {
        cudaStreamCreateWithFlags(&s2, cudaStreamNonBlocking);
        cudaEventCreateWithFlags(&evF, cudaEventDisableTiming);
        cudaEventCreateWithFlags(&evJ, cudaEventDisableTiming);
    }

    /* fork: CSR build + W2 split run concurrently with x/W1 splits + gemm1 */
    cudaEventRecord(evF, 0);
    cudaStreamWaitEvent(s2, evF, 0);
    zero_counts<<<(N_NODES + 255) / 256, 256, 0, s2>>>();
    count_deg<<<(NE_TOT + 255) / 256, 256, 0, s2>>>(ei);
    scan_rowptr<<<1, 1024, 0, s2>>>();
    scatter_edges<<<(NE_TOT + 255) / 256, 256, 0, s2>>>(ei);
    split_w_t<<<(L1_F * OUT_CH + 255) / 256, 256, 0, s2>>>(W2, w2hi, w2lo, L1_F, OUT_CH);
    cudaEventRecord(evJ, s2);

    /* main stream: conversions, gemm1, attn1 */
    split_fp32<<<(N_NODES * IN_CH + 255) / 256, 256>>>(x, xhi, xlo, N_NODES * IN_CH);
    split_w_t<<<(IN_CH * L1_F + 255) / 256, 256>>>(W1, w1hi, w1lo, IN_CH, L1_F);
    gemm_hmma<<<dim3(L1_F / 128, 157), 256>>>(xhi, xlo, w1hi, w1lo, h1f, N_NODES, L1_F);
    attn_coef<HEADS, HID><<<(N_NODES * HEADS + 7) / 8, 256>>>(h1f, a_src1, a_dst1, as1, ad1);

    /* join: need CSR (and W2 split) before aggregation / gemm2 */
    cudaStreamWaitEvent(0, evJ, 0);
    fused_agg<HEADS, HID, true, true><<<(N_NODES * HEADS + 7) / 8, 256>>>(
        as1, ad1, h1f, b1, out + A1_OFF, nullptr, a1hi, a1lo);

    /* layer 2 */
    gemm_hmma<<<dim3(OUT_CH / 128, 157), 256>>>(a1hi, a1lo, w2hi, w2lo, h2f, N_NODES, OUT_CH);
    attn_coef<1, OUT_CH><<<(N_NODES + 7) / 8, 256>>>(h2f, a_src2, a_dst2, as2, ad2);
    fused_agg<1, OUT_CH, false, false><<<(N_NODES + 7) / 8, 256>>>(
        as2, ad2, h2f, b2, out + A2_OFF, out, nullptr, nullptr);
}

// round 14
// speedup vs baseline: 1.4642x; 1.1433x over previous
#include <cuda_runtime.h>
#include <cuda_fp16.h>
#include <math.h>
#include <stdint.h>

#define N_NODES 20000
#define N_EDGES 320000
#define NE_TOT  (N_EDGES + N_NODES)   /* 340000 incl self loops */
#define IN_CH   512
#define HID     128
#define HEADS   4
#define OUT_CH  256
#define L1_F    (HEADS * HID)         /* 512 */

#define A1_OFF  (N_NODES * OUT_CH)            /* 5,120,000 */
#define A2_OFF  (A1_OFF + NE_TOT * HEADS)     /* 6,480,000 */

/* ------------------------- scratch (device globals) ------------------------- */
__device__ __half g_h1f[(size_t)N_NODES * L1_F];   /* h1, fp16 */
__device__ __half g_h2f[(size_t)N_NODES * OUT_CH]; /* h2, fp16 */
__device__ __half g_xhi[(size_t)N_NODES * IN_CH];
__device__ __half g_xlo[(size_t)N_NODES * IN_CH];
__device__ __half g_w1h[L1_F * IN_CH];             /* transposed [N][K], fp16 */
__device__ __half g_w2h[OUT_CH * L1_F];
__device__ __half g_a1hi[(size_t)N_NODES * L1_F];
__device__ __half g_a1lo[(size_t)N_NODES * L1_F];
__device__ float g_as1[N_NODES * HEADS];
__device__ float g_ad1[N_NODES * HEADS];
__device__ float g_as2[N_NODES];
__device__ float g_ad2[N_NODES];
__device__ float g_vbuf[(size_t)NE_TOT * HEADS];   /* [head][csr_pos] */
__device__ int   g_counts[N_NODES];
__device__ int   g_cursor[N_NODES];
__device__ int   g_rowptr[N_NODES + 1];
__device__ int   g_esrc[NE_TOT];
__device__ int   g_eorig[NE_TOT];

/* ------------------------- helpers ------------------------- */
__device__ __forceinline__ uint32_t smem_u32(const void* p) {
    uint32_t a;
    asm("{ .reg .u64 t; cvta.to.shared.u64 t, %1; cvt.u32.u64 %0, t; }" : "=r"(a) : "l"(p));
    return a;
}
__device__ __forceinline__ void ldsm_x4(uint32_t& r0, uint32_t& r1, uint32_t& r2,
                                        uint32_t& r3, uint32_t addr) {
    asm volatile("ldmatrix.sync.aligned.m8n8.x4.shared.b16 {%0,%1,%2,%3}, [%4];"
                 : "=r"(r0), "=r"(r1), "=r"(r2), "=r"(r3) : "r"(addr));
}
__device__ __forceinline__ void mma_f16(float* d, const uint32_t* a, const uint32_t* b) {
    asm volatile("mma.sync.aligned.m16n8k16.row.col.f32.f16.f16.f32 "
                 "{%0,%1,%2,%3}, {%4,%5,%6,%7}, {%8,%9}, {%0,%1,%2,%3};"
                 : "+f"(d[0]), "+f"(d[1]), "+f"(d[2]), "+f"(d[3])
                 : "r"(a[0]), "r"(a[1]), "r"(a[2]), "r"(a[3]), "r"(b[0]), "r"(b[1]));
}
__device__ __forceinline__ void cpa16(uint32_t dst, const void* src) {
    asm volatile("cp.async.cg.shared.global [%0], [%1], 16;" :: "r"(dst), "l"(src));
}
#define CP_COMMIT() asm volatile("cp.async.commit_group;" ::: "memory")
#define CP_WAIT0()  asm volatile("cp.async.wait_group 0;" ::: "memory")

/* ------------------------- CSR construction ------------------------- */
__device__ __forceinline__ void edge_nodes(const int* __restrict__ ei, int e,
                                           int& src, int& dst) {
    if (e < N_EDGES) { src = ei[e]; dst = ei[N_EDGES + e]; }
    else             { src = dst = e - N_EDGES; }
}

__global__ void zero_counts() {
    int i = blockIdx.x * blockDim.x + threadIdx.x;
    if (i < N_NODES) { g_counts[i] = 0; g_cursor[i] = 0; }
}

__global__ void count_deg(const int* __restrict__ ei) {
    int e = blockIdx.x * blockDim.x + threadIdx.x;
    if (e >= NE_TOT) return;
    int src, dst;
    edge_nodes(ei, e, src, dst);
    atomicAdd(&g_counts[dst], 1);
}

__global__ void scan_rowptr() {
    __shared__ int wsum[32];
    __shared__ int s_carry;
    int tid = threadIdx.x, lane = tid & 31, wid = tid >> 5;
    if (tid == 0) { g_rowptr[0] = 0; s_carry = 0; }
    __syncthreads();
    for (int base = 0; base < N_NODES; base += 1024) {
        int i = base + tid;
        int v = (i < N_NODES) ? g_counts[i] : 0;
        int x = v;
#pragma unroll
        for (int o = 1; o < 32; o <<= 1) {
            int t = __shfl_up_sync(0xFFFFFFFFu, x, o);
            if (lane >= o) x += t;
        }
        if (lane == 31) wsum[wid] = x;
        __syncthreads();
        if (wid == 0) {
            int s = wsum[lane];
#pragma unroll
            for (int o = 1; o < 32; o <<= 1) {
                int t = __shfl_up_sync(0xFFFFFFFFu, s, o);
                if (lane >= o) s += t;
            }
            wsum[lane] = s;
        }
        __syncthreads();
        int inc = x + (wid > 0 ? wsum[wid - 1] : 0) + s_carry;
        if (i < N_NODES) g_rowptr[i + 1] = inc;
        __syncthreads();
        if (tid == 1023) s_carry = inc;
        __syncthreads();
    }
}

__global__ void scatter_edges(const int* __restrict__ ei) {
    int e = blockIdx.x * blockDim.x + threadIdx.x;
    if (e >= NE_TOT) return;
    int src, dst;
    edge_nodes(ei, e, src, dst);
    int pos = g_rowptr[dst] + atomicAdd(&g_cursor[dst], 1);
    g_esrc[pos]  = src;
    g_eorig[pos] = e;
}

/* ------------------------- fp32 -> fp16 hi/lo split ------------------------- */
__global__ void split_fp32(const float* __restrict__ in,
                           __half* __restrict__ hi,
                           __half* __restrict__ lo, int n) {
    int i = blockIdx.x * blockDim.x + threadIdx.x;
    if (i >= n) return;
    float v = in[i];
    __half h = __float2half_rn(v);
    hi[i] = h;
    lo[i] = __float2half_rn(v - __half2float(h));
}

/* W [K][N] -> out [N][K] fp16 (single plane) */
__global__ void cvt_w_t(const float* __restrict__ W,
                        __half* __restrict__ t, int K, int N) {
    int i = blockIdx.x * blockDim.x + threadIdx.x;
    if (i >= K * N) return;
    int k = i / N, n = i % N;
    t[n * K + k] = __float2half_rn(W[i]);
}

/* ------------------------- HMMA fp16 2-product GEMM -------------------------
   C[M,N] ≈ Ahi*B^T + Alo*B^T; A hi/lo fp16 [M,K], B fp16 [N,K].
   K=512. CTA tile 128x128, 8 warps, 2-buffer cp.async, wait0.
   Output written fp16. Per stage: 3 plane loads, 32 MMAs/warp. */
#define KSTAGES (512 / 16)    /* 32 */
#define SROW    24

__global__ __launch_bounds__(256)
void gemm_hmma(const __half* __restrict__ Ahi, const __half* __restrict__ Alo,
               const __half* __restrict__ B,
               __half* __restrict__ Cf, int M, int N) {
    __shared__ __align__(16) __half sA[2][2][128][SROW]; /* [buf][hi/lo] */
    __shared__ __align__(16) __half sB[2][128][SROW];    /* [buf] */

    int tid = threadIdx.x, wid = tid >> 5, lane = tid & 31;
    int m0 = blockIdx.y * 128, n0 = blockIdx.x * 128;
    int wm = (wid >> 1) * 32;
    int wn = (wid & 1) * 64;

    int prow = tid >> 1, pseg = tid & 1;
    int agr = m0 + prow; if (agr >= M) agr = M - 1;
    const __half* pAhi = Ahi + (size_t)agr * 512 + pseg * 8;
    const __half* pAlo = Alo + (size_t)agr * 512 + pseg * 8;
    const __half* pB   = B   + (size_t)(n0 + prow) * 512 + pseg * 8;
    uint32_t dA0[2], dA1[2], dB[2];
#pragma unroll
    for (int b = 0; b < 2; b++) {
        dA0[b] = smem_u32(&sA[b][0][prow][pseg * 8]);
        dA1[b] = smem_u32(&sA[b][1][prow][pseg * 8]);
        dB[b]  = smem_u32(&sB[b][prow][pseg * 8]);
    }

    int a_row = (lane & 15), a_k = (lane >> 4) * 8;
    int b_nrow = ((lane >> 4) << 3) + (lane & 7), b_k = ((lane >> 3) & 1) * 8;
    uint32_t a_base0 = smem_u32(&sA[0][0][wm + a_row][a_k]);
    uint32_t a_base1 = smem_u32(&sA[0][1][wm + a_row][a_k]);
    uint32_t b_base  = smem_u32(&sB[0][wn + b_nrow][b_k]);
    const uint32_t ABUF = 2 * 128 * SROW * 2;   /* bytes per A buffer */
    const uint32_t BBUF = 128 * SROW * 2;       /* bytes per B buffer */

    float acc[2][8][4];
#pragma unroll
    for (int i = 0; i < 2; i++)
#pragma unroll
        for (int j = 0; j < 8; j++)
#pragma unroll
            for (int q = 0; q < 4; q++) acc[i][j][q] = 0.f;

    cpa16(dA0[0], pAhi);
    cpa16(dA1[0], pAlo);
    cpa16(dB[0],  pB);
    CP_COMMIT();
    CP_WAIT0();
    __syncthreads();

    for (int t = 0; t < KSTAGES; t++) {
        int buf = t & 1;
        if (t + 1 < KSTAGES) {
            int nb = (t + 1) & 1, ko = (t + 1) * 16;
            cpa16(dA0[nb], pAhi + ko);
            cpa16(dA1[nb], pAlo + ko);
            cpa16(dB[nb],  pB + ko);
            CP_COMMIT();
        }

        uint32_t ahi[2][4], alo[2][4];
#pragma unroll
        for (int ma = 0; ma < 2; ma++) {
            ldsm_x4(ahi[ma][0], ahi[ma][1], ahi[ma][2], ahi[ma][3],
                    a_base0 + buf * ABUF + ma * 16 * SROW * 2);
            ldsm_x4(alo[ma][0], alo[ma][1], alo[ma][2], alo[ma][3],
                    a_base1 + buf * ABUF + ma * 16 * SROW * 2);
        }
        uint32_t bf[4][4];
#pragma unroll
        for (int g = 0; g < 4; g++)
            ldsm_x4(bf[g][0], bf[g][1], bf[g][2], bf[g][3],
                    b_base + buf * BBUF + g * 16 * SROW * 2);

#pragma unroll
        for (int ma = 0; ma < 2; ma++)
#pragma unroll
            for (int g = 0; g < 4; g++)
#pragma unroll
                for (int h = 0; h < 2; h++) {
                    float* d = acc[ma][g * 2 + h];
                    mma_f16(d, ahi[ma], &bf[g][h * 2]);
                    mma_f16(d, alo[ma], &bf[g][h * 2]);
                }

        CP_WAIT0();
        __syncthreads();
    }

    /* epilogue: fp16 C */
    int lg = lane >> 2, lt = lane & 3;
#pragma unroll
    for (int ma = 0; ma < 2; ma++) {
        int mrow0 = m0 + wm + ma * 16 + lg;
#pragma unroll
        for (int nb = 0; nb < 8; nb++) {
            int n = n0 + wn + nb * 8 + lt * 2;
            float* d = acc[ma][nb];
            if (mrow0 < M)
                *(__half2*)(Cf + (size_t)mrow0 * N + n) = __floats2half2_rn(d[0], d[1]);
            if (mrow0 + 8 < M)
                *(__half2*)(Cf + (size_t)(mrow0 + 8) * N + n) = __floats2half2_rn(d[2], d[3]);
        }
    }
}

/* ------------------------- attention coefficients (fp16 h) ----------------- */
template <int H, int C>
__global__ void attn_coef(const __half* __restrict__ h,
                          const float* __restrict__ a_src,
                          const float* __restrict__ a_dst,
                          float* __restrict__ as, float* __restrict__ ad) {
    int gw = (blockIdx.x * blockDim.x + threadIdx.x) >> 5;
    int lane = threadIdx.x & 31;
    if (gw >= N_NODES * H) return;
    int n = gw / H, hh = gw % H;
    const __half2* hp = (const __half2*)(h + (size_t)n * (H * C) + hh * C);
    const float* sp = a_src + hh * C;
    const float* dp = a_dst + hh * C;
    float s = 0.f, d = 0.f;
#pragma unroll
    for (int r = 0; r < C / 64; r++) {
        int c2 = lane + 32 * r;
        float2 f = __half22float2(hp[c2]);
        s += f.x * sp[c2 * 2] + f.y * sp[c2 * 2 + 1];
        d += f.x * dp[c2 * 2] + f.y * dp[c2 * 2 + 1];
    }
#pragma unroll
    for (int o = 16; o; o >>= 1) {
        s += __shfl_xor_sync(0xFFFFFFFFu, s, o);
        d += __shfl_xor_sync(0xFFFFFFFFu, d, o);
    }
    if (lane == 0) { as[gw] = s; ad[gw] = d; }
}

/* ------------------------- fused softmax + aggregate (fp16 gather) --------- */
template <int H, int C, bool ELU, bool SPLIT>
__global__ __launch_bounds__(256)
void fused_agg(const float* __restrict__ as, const float* __restrict__ ad,
               const __half* __restrict__ hfeat_h, const float* __restrict__ bias,
               float* __restrict__ alpha_out, float* __restrict__ aggout,
               __half* __restrict__ ohi, __half* __restrict__ olo) {
    int gw = (blockIdx.x * blockDim.x + threadIdx.x) >> 5;
    int lane = threadIdx.x & 31;
    if (gw >= N_NODES * H) return;
    int dst = gw / H, hh = gw % H;

    int beg = g_rowptr[dst], end = g_rowptr[dst + 1];
    float adv = ad[dst * H + hh];
    float* vb = g_vbuf + (size_t)hh * NE_TOT;

    /* pass 1: gather logits once, store contiguously, track max */
    float mx = -1e30f;
    for (int i = beg + lane; i < end; i += 32) {
        float v = as[g_esrc[i] * H + hh] + adv;
        v = v > 0.f ? v : 0.2f * v;
        vb[i] = v;
        mx = fmaxf(mx, v);
    }
#pragma unroll
    for (int o = 16; o; o >>= 1) mx = fmaxf(mx, __shfl_xor_sync(0xFFFFFFFFu, mx, o));

    /* pass 2: denom */
    float sm = 0.f;
    for (int i = beg + lane; i < end; i += 32) sm += __expf(vb[i] - mx);
#pragma unroll
    for (int o = 16; o; o >>= 1) sm += __shfl_xor_sync(0xFFFFFFFFu, sm, o);
    float inv = 1.f / sm;

    /* pass 3: alpha + gather-accumulate (software pipelined, depth 2) */
    constexpr int R = C / 128;
    float4 acc[R];
#pragma unroll
    for (int r = 0; r < R; r++) acc[r] = make_float4(0.f, 0.f, 0.f, 0.f);

    auto load_feats = [&](int s, float4* t) {
        const uint2* hp = (const uint2*)(hfeat_h + (size_t)s * (H * C) + hh * C);
#pragma unroll
        for (int r = 0; r < R; r++) {
            uint2 u = hp[lane + 32 * r];
            float2 f01 = __half22float2(*(__half2*)&u.x);
            float2 f23 = __half22float2(*(__half2*)&u.y);
            t[r] = make_float4(f01.x, f01.y, f23.x, f23.y);
        }
    };

    int i = beg;
    int eo = g_eorig[i];
    float vv = vb[i];
    float4 tv[R];
    load_feats(g_esrc[i], tv);
    for (;;) {
        int inext = i + 1;
        bool more = inext < end;
        int eo2 = 0;
        float vv2 = 0.f;
        float4 tv2[R];
        if (more) {
            eo2 = g_eorig[inext];
            vv2 = vb[inext];
            load_feats(g_esrc[inext], tv2);
        }
        float a = __expf(vv - mx) * inv;
        if (lane == 0) alpha_out[eo * H + hh] = a;
#pragma unroll
        for (int r = 0; r < R; r++) {
            acc[r].x += a * tv[r].x;
            acc[r].y += a * tv[r].y;
            acc[r].z += a * tv[r].z;
            acc[r].w += a * tv[r].w;
        }
        if (!more) break;
        eo = eo2; vv = vv2;
#pragma unroll
        for (int r = 0; r < R; r++) tv[r] = tv2[r];
        i = inext;
    }

    /* epilogue: bias (+ELU), fp32 out or fp16 hi/lo split */
#pragma unroll
    for (int r = 0; r < R; r++) {
        int c = (lane + 32 * r) * 4;
        const float* bp = bias + hh * C + c;
        float4 o = acc[r];
        o.x += bp[0]; o.y += bp[1]; o.z += bp[2]; o.w += bp[3];
        if (ELU) {
            o.x = o.x > 0.f ? o.x : expm1f(o.x);
            o.y = o.y > 0.f ? o.y : expm1f(o.y);
            o.z = o.z > 0.f ? o.z : expm1f(o.z);
            o.w = o.w > 0.f ? o.w : expm1f(o.w);
        }
        if (SPLIT) {
            size_t base = (size_t)dst * (H * C) + hh * C + c;
            float vv4[4] = { o.x, o.y, o.z, o.w };
#pragma unroll
            for (int q = 0; q < 4; q++) {
                __half h = __float2half_rn(vv4[q]);
                ohi[base + q] = h;
                olo[base + q] = __float2half_rn(vv4[q] - __half2float(h));
            }
        } else {
            float* op = aggout + (size_t)dst * (H * C) + hh * C;
            ((float4*)op)[lane + 32 * r] = o;
        }
    }
}

/* ------------------------- launch ------------------------- */
extern "C" void kernel_launch(void* const* d_in, const int* in_sizes, int n_in,
                              void* d_out, int out_size) {
    const float* x      = (const float*)d_in[0];
    const int*   ei     = (const int*)  d_in[1];
    const float* W1     = (const float*)d_in[2];
    const float* a_src1 = (const float*)d_in[3];
    const float* a_dst1 = (const float*)d_in[4];
    const float* b1     = (const float*)d_in[5];
    const float* W2     = (const float*)d_in[6];
    const float* a_src2 = (const float*)d_in[7];
    const float* a_dst2 = (const float*)d_in[8];
    const float* b2     = (const float*)d_in[9];
    float* out = (float*)d_out;

    float *as1, *ad1, *as2, *ad2;
    __half *h1f, *h2f, *xhi, *xlo, *w1h, *w2h, *a1hi, *a1lo;
    cudaGetSymbolAddress((void**)&h1f,  g_h1f);
    cudaGetSymbolAddress((void**)&h2f,  g_h2f);
    cudaGetSymbolAddress((void**)&as1,  g_as1);
    cudaGetSymbolAddress((void**)&ad1,  g_ad1);
    cudaGetSymbolAddress((void**)&as2,  g_as2);
    cudaGetSymbolAddress((void**)&ad2,  g_ad2);
    cudaGetSymbolAddress((void**)&xhi,  g_xhi);
    cudaGetSymbolAddress((void**)&xlo,  g_xlo);
    cudaGetSymbolAddress((void**)&w1h,  g_w1h);
    cudaGetSymbolAddress((void**)&w2h,  g_w2h);
    cudaGetSymbolAddress((void**)&a1hi, g_a1hi);
    cudaGetSymbolAddress((void**)&a1lo, g_a1lo);

    /* second stream + fork/join events (created once, before first capture) */
    static cudaStream_t s2 = nullptr;
    static cudaEvent_t evF = nullptr, evJ = nullptr;
    if (!s2) {
        cudaStreamCreateWithFlags(&s2, cudaStreamNonBlocking);
        cudaEventCreateWithFlags(&evF, cudaEventDisableTiming);
        cudaEventCreateWithFlags(&evJ, cudaEventDisableTiming);
    }

    /* fork: CSR build + W2 convert run concurrently with x/W1 + gemm1 */
    cudaEventRecord(evF, 0);
    cudaStreamWaitEvent(s2, evF, 0);
    zero_counts<<<(N_NODES + 255) / 256, 256, 0, s2>>>();
    count_deg<<<(NE_TOT + 255) / 256, 256, 0, s2>>>(ei);
    scan_rowptr<<<1, 1024, 0, s2>>>();
    scatter_edges<<<(NE_TOT + 255) / 256, 256, 0, s2>>>(ei);
    cvt_w_t<<<(L1_F * OUT_CH + 255) / 256, 256, 0, s2>>>(W2, w2h, L1_F, OUT_CH);
    cudaEventRecord(evJ, s2);

    /* main stream: conversions, gemm1, attn1 */
    split_fp32<<<(N_NODES * IN_CH + 255) / 256, 256>>>(x, xhi, xlo, N_NODES * IN_CH);
    cvt_w_t<<<(IN_CH * L1_F + 255) / 256, 256>>>(W1, w1h, IN_CH, L1_F);
    gemm_hmma<<<dim3(L1_F / 128, 157), 256>>>(xhi, xlo, w1h, h1f, N_NODES, L1_F);
    attn_coef<HEADS, HID><<<(N_NODES * HEADS + 7) / 8, 256>>>(h1f, a_src1, a_dst1, as1, ad1);

    /* join: need CSR (and W2) before aggregation / gemm2 */
    cudaStreamWaitEvent(0, evJ, 0);
    fused_agg<HEADS, HID, true, true><<<(N_NODES * HEADS + 7) / 8, 256>>>(
        as1, ad1, h1f, b1, out + A1_OFF, nullptr, a1hi, a1lo);

    /* layer 2 */
    gemm_hmma<<<dim3(OUT_CH / 128, 157), 256>>>(a1hi, a1lo, w2h, h2f, N_NODES, OUT_CH);
    attn_coef<1, OUT_CH><<<(N_NODES + 7) / 8, 256>>>(h2f, a_src2, a_dst2, as2, ad2);
    fused_agg<1, OUT_CH, false, false><<<(N_NODES + 7) / 8, 256>>>(
        as2, ad2, h2f, b2, out + A2_OFF, out, nullptr, nullptr);
}

// round 15
// speedup vs baseline: 1.5631x; 1.0675x over previous
#include <cuda_runtime.h>
#include <cuda_fp16.h>
#include <math.h>
#include <stdint.h>

#define N_NODES 20000
#define N_EDGES 320000
#define NE_TOT  (N_EDGES + N_NODES)   /* 340000 incl self loops */
#define IN_CH   512
#define HID     128
#define HEADS   4
#define OUT_CH  256
#define L1_F    (HEADS * HID)         /* 512 */

#define A1_OFF  (N_NODES * OUT_CH)            /* 5,120,000 */
#define A2_OFF  (A1_OFF + NE_TOT * HEADS)     /* 6,480,000 */

/* ------------------------- scratch (device globals) ------------------------- */
__device__ __half g_h1f[(size_t)N_NODES * L1_F];   /* h1, fp16 */
__device__ __half g_h2f[(size_t)N_NODES * OUT_CH]; /* h2, fp16 */
__device__ __half g_xf[(size_t)N_NODES * IN_CH];   /* x,  fp16 */
__device__ __half g_w1h[L1_F * IN_CH];             /* transposed [N][K], fp16 */
__device__ __half g_w2h[OUT_CH * L1_F];
__device__ __half g_a1f[(size_t)N_NODES * L1_F];   /* agg1, fp16 */
__device__ float g_as1[N_NODES * HEADS];
__device__ float g_ad1[N_NODES * HEADS];
__device__ float g_as2[N_NODES];
__device__ float g_ad2[N_NODES];
__device__ float g_vbuf[(size_t)NE_TOT * HEADS];   /* [head][csr_pos] */
__device__ int   g_counts[N_NODES];
__device__ int   g_cursor[N_NODES];
__device__ int   g_rowptr[N_NODES + 1];
__device__ int   g_esrc[NE_TOT];
__device__ int   g_eorig[NE_TOT];

/* ------------------------- helpers ------------------------- */
__device__ __forceinline__ uint32_t smem_u32(const void* p) {
    uint32_t a;
    asm("{ .reg .u64 t; cvta.to.shared.u64 t, %1; cvt.u32.u64 %0, t; }" : "=r"(a) : "l"(p));
    return a;
}
__device__ __forceinline__ void ldsm_x4(uint32_t& r0, uint32_t& r1, uint32_t& r2,
                                        uint32_t& r3, uint32_t addr) {
    asm volatile("ldmatrix.sync.aligned.m8n8.x4.shared.b16 {%0,%1,%2,%3}, [%4];"
                 : "=r"(r0), "=r"(r1), "=r"(r2), "=r"(r3) : "r"(addr));
}
__device__ __forceinline__ void mma_f16(float* d, const uint32_t* a, const uint32_t* b) {
    asm volatile("mma.sync.aligned.m16n8k16.row.col.f32.f16.f16.f32 "
                 "{%0,%1,%2,%3}, {%4,%5,%6,%7}, {%8,%9}, {%0,%1,%2,%3};"
                 : "+f"(d[0]), "+f"(d[1]), "+f"(d[2]), "+f"(d[3])
                 : "r"(a[0]), "r"(a[1]), "r"(a[2]), "r"(a[3]), "r"(b[0]), "r"(b[1]));
}
__device__ __forceinline__ void cpa16(uint32_t dst, const void* src) {
    asm volatile("cp.async.cg.shared.global [%0], [%1], 16;" :: "r"(dst), "l"(src));
}
#define CP_COMMIT() asm volatile("cp.async.commit_group;" ::: "memory")
#define CP_WAIT0()  asm volatile("cp.async.wait_group 0;" ::: "memory")

/* ------------------------- CSR construction ------------------------- */
__device__ __forceinline__ void edge_nodes(const int* __restrict__ ei, int e,
                                           int& src, int& dst) {
    if (e < N_EDGES) { src = ei[e]; dst = ei[N_EDGES + e]; }
    else             { src = dst = e - N_EDGES; }
}

__global__ void zero_counts() {
    int i = blockIdx.x * blockDim.x + threadIdx.x;
    if (i < N_NODES) { g_counts[i] = 0; g_cursor[i] = 0; }
}

__global__ void count_deg(const int* __restrict__ ei) {
    int e = blockIdx.x * blockDim.x + threadIdx.x;
    if (e >= NE_TOT) return;
    int src, dst;
    edge_nodes(ei, e, src, dst);
    atomicAdd(&g_counts[dst], 1);
}

__global__ void scan_rowptr() {
    __shared__ int wsum[32];
    __shared__ int s_carry;
    int tid = threadIdx.x, lane = tid & 31, wid = tid >> 5;
    if (tid == 0) { g_rowptr[0] = 0; s_carry = 0; }
    __syncthreads();
    for (int base = 0; base < N_NODES; base += 1024) {
        int i = base + tid;
        int v = (i < N_NODES) ? g_counts[i] : 0;
        int x = v;
#pragma unroll
        for (int o = 1; o < 32; o <<= 1) {
            int t = __shfl_up_sync(0xFFFFFFFFu, x, o);
            if (lane >= o) x += t;
        }
        if (lane == 31) wsum[wid] = x;
        __syncthreads();
        if (wid == 0) {
            int s = wsum[lane];
#pragma unroll
            for (int o = 1; o < 32; o <<= 1) {
                int t = __shfl_up_sync(0xFFFFFFFFu, s, o);
                if (lane >= o) s += t;
            }
            wsum[lane] = s;
        }
        __syncthreads();
        int inc = x + (wid > 0 ? wsum[wid - 1] : 0) + s_carry;
        if (i < N_NODES) g_rowptr[i + 1] = inc;
        __syncthreads();
        if (tid == 1023) s_carry = inc;
        __syncthreads();
    }
}

__global__ void scatter_edges(const int* __restrict__ ei) {
    int e = blockIdx.x * blockDim.x + threadIdx.x;
    if (e >= NE_TOT) return;
    int src, dst;
    edge_nodes(ei, e, src, dst);
    int pos = g_rowptr[dst] + atomicAdd(&g_cursor[dst], 1);
    g_esrc[pos]  = src;
    g_eorig[pos] = e;
}

/* ------------------------- fp32 -> fp16 converts ------------------------- */
__global__ void cvt_fp32(const float* __restrict__ in, __half* __restrict__ o, int n) {
    int i = blockIdx.x * blockDim.x + threadIdx.x;
    if (i >= n) return;
    o[i] = __float2half_rn(in[i]);
}

/* W [K][N] -> out [N][K] fp16 */
__global__ void cvt_w_t(const float* __restrict__ W,
                        __half* __restrict__ t, int K, int N) {
    int i = blockIdx.x * blockDim.x + threadIdx.x;
    if (i >= K * N) return;
    int k = i / N, n = i % N;
    t[n * K + k] = __float2half_rn(W[i]);
}

/* ------------------------- HMMA fp16 GEMM -------------------------
   C[M,N] = A*B^T; A fp16 [M,K], B fp16 [N,K]. K=512.
   CTA tile 128x128, 8 warps, 2-buffer cp.async, wait0. fp16 output. */
#define KSTAGES (512 / 16)    /* 32 */
#define SROW    24

__global__ __launch_bounds__(256)
void gemm_hmma(const __half* __restrict__ A, const __half* __restrict__ B,
               __half* __restrict__ Cf, int M, int N) {
    __shared__ __align__(16) __half sA[2][128][SROW];
    __shared__ __align__(16) __half sB[2][128][SROW];

    int tid = threadIdx.x, wid = tid >> 5, lane = tid & 31;
    int m0 = blockIdx.y * 128, n0 = blockIdx.x * 128;
    int wm = (wid >> 1) * 32;
    int wn = (wid & 1) * 64;

    int prow = tid >> 1, pseg = tid & 1;
    int agr = m0 + prow; if (agr >= M) agr = M - 1;
    const __half* pA = A + (size_t)agr * 512 + pseg * 8;
    const __half* pB = B + (size_t)(n0 + prow) * 512 + pseg * 8;
    uint32_t dA[2], dB[2];
#pragma unroll
    for (int b = 0; b < 2; b++) {
        dA[b] = smem_u32(&sA[b][prow][pseg * 8]);
        dB[b] = smem_u32(&sB[b][prow][pseg * 8]);
    }

    int a_row = (lane & 15), a_k = (lane >> 4) * 8;
    int b_nrow = ((lane >> 4) << 3) + (lane & 7), b_k = ((lane >> 3) & 1) * 8;
    uint32_t a_base = smem_u32(&sA[0][wm + a_row][a_k]);
    uint32_t b_base = smem_u32(&sB[0][wn + b_nrow][b_k]);
    const uint32_t BUF = 128 * SROW * 2;   /* bytes per buffer */

    float acc[2][8][4];
#pragma unroll
    for (int i = 0; i < 2; i++)
#pragma unroll
        for (int j = 0; j < 8; j++)
#pragma unroll
            for (int q = 0; q < 4; q++) acc[i][j][q] = 0.f;

    cpa16(dA[0], pA);
    cpa16(dB[0], pB);
    CP_COMMIT();
    CP_WAIT0();
    __syncthreads();

    for (int t = 0; t < KSTAGES; t++) {
        int buf = t & 1;
        if (t + 1 < KSTAGES) {
            int nb = (t + 1) & 1, ko = (t + 1) * 16;
            cpa16(dA[nb], pA + ko);
            cpa16(dB[nb], pB + ko);
            CP_COMMIT();
        }

        uint32_t af[2][4];
#pragma unroll
        for (int ma = 0; ma < 2; ma++)
            ldsm_x4(af[ma][0], af[ma][1], af[ma][2], af[ma][3],
                    a_base + buf * BUF + ma * 16 * SROW * 2);
        uint32_t bf[4][4];
#pragma unroll
        for (int g = 0; g < 4; g++)
            ldsm_x4(bf[g][0], bf[g][1], bf[g][2], bf[g][3],
                    b_base + buf * BUF + g * 16 * SROW * 2);

#pragma unroll
        for (int ma = 0; ma < 2; ma++)
#pragma unroll
            for (int g = 0; g < 4; g++)
#pragma unroll
                for (int h = 0; h < 2; h++)
                    mma_f16(acc[ma][g * 2 + h], af[ma], &bf[g][h * 2]);

        CP_WAIT0();
        __syncthreads();
    }

    /* epilogue: fp16 C */
    int lg = lane >> 2, lt = lane & 3;
#pragma unroll
    for (int ma = 0; ma < 2; ma++) {
        int mrow0 = m0 + wm + ma * 16 + lg;
#pragma unroll
        for (int nb = 0; nb < 8; nb++) {
            int n = n0 + wn + nb * 8 + lt * 2;
            float* d = acc[ma][nb];
            if (mrow0 < M)
                *(__half2*)(Cf + (size_t)mrow0 * N + n) = __floats2half2_rn(d[0], d[1]);
            if (mrow0 + 8 < M)
                *(__half2*)(Cf + (size_t)(mrow0 + 8) * N + n) = __floats2half2_rn(d[2], d[3]);
        }
    }
}

/* ------------------------- attention coefficients (fp16 h) ----------------- */
template <int H, int C>
__global__ void attn_coef(const __half* __restrict__ h,
                          const float* __restrict__ a_src,
                          const float* __restrict__ a_dst,
                          float* __restrict__ as, float* __restrict__ ad) {
    int gw = (blockIdx.x * blockDim.x + threadIdx.x) >> 5;
    int lane = threadIdx.x & 31;
    if (gw >= N_NODES * H) return;
    int n = gw / H, hh = gw % H;
    const __half2* hp = (const __half2*)(h + (size_t)n * (H * C) + hh * C);
    const float* sp = a_src + hh * C;
    const float* dp = a_dst + hh * C;
    float s = 0.f, d = 0.f;
#pragma unroll
    for (int r = 0; r < C / 64; r++) {
        int c2 = lane + 32 * r;
        float2 f = __half22float2(hp[c2]);
        s += f.x * sp[c2 * 2] + f.y * sp[c2 * 2 + 1];
        d += f.x * dp[c2 * 2] + f.y * dp[c2 * 2 + 1];
    }
#pragma unroll
    for (int o = 16; o; o >>= 1) {
        s += __shfl_xor_sync(0xFFFFFFFFu, s, o);
        d += __shfl_xor_sync(0xFFFFFFFFu, d, o);
    }
    if (lane == 0) { as[gw] = s; ad[gw] = d; }
}

/* ------------------------- fused softmax + aggregate (fp16 gather) --------- */
template <int H, int C, bool ELU, bool SPLIT>
__global__ __launch_bounds__(256)
void fused_agg(const float* __restrict__ as, const float* __restrict__ ad,
               const __half* __restrict__ hfeat_h, const float* __restrict__ bias,
               float* __restrict__ alpha_out, float* __restrict__ aggout,
               __half* __restrict__ of16) {
    int gw = (blockIdx.x * blockDim.x + threadIdx.x) >> 5;
    int lane = threadIdx.x & 31;
    if (gw >= N_NODES * H) return;
    int dst = gw / H, hh = gw % H;

    int beg = g_rowptr[dst], end = g_rowptr[dst + 1];
    float adv = ad[dst * H + hh];
    float* vb = g_vbuf + (size_t)hh * NE_TOT;

    /* pass 1: gather logits once, store contiguously, track max */
    float mx = -1e30f;
    for (int i = beg + lane; i < end; i += 32) {
        float v = as[g_esrc[i] * H + hh] + adv;
        v = v > 0.f ? v : 0.2f * v;
        vb[i] = v;
        mx = fmaxf(mx, v);
    }
#pragma unroll
    for (int o = 16; o; o >>= 1) mx = fmaxf(mx, __shfl_xor_sync(0xFFFFFFFFu, mx, o));

    /* pass 2: denom */
    float sm = 0.f;
    for (int i = beg + lane; i < end; i += 32) sm += __expf(vb[i] - mx);
#pragma unroll
    for (int o = 16; o; o >>= 1) sm += __shfl_xor_sync(0xFFFFFFFFu, sm, o);
    float inv = 1.f / sm;

    /* pass 3: alpha + gather-accumulate (software pipelined, depth 2) */
    constexpr int R = C / 128;
    float4 acc[R];
#pragma unroll
    for (int r = 0; r < R; r++) acc[r] = make_float4(0.f, 0.f, 0.f, 0.f);

    auto load_feats = [&](int s, float4* t) {
        const uint2* hp = (const uint2*)(hfeat_h + (size_t)s * (H * C) + hh * C);
#pragma unroll
        for (int r = 0; r < R; r++) {
            uint2 u = hp[lane + 32 * r];
            float2 f01 = __half22float2(*(__half2*)&u.x);
            float2 f23 = __half22float2(*(__half2*)&u.y);
            t[r] = make_float4(f01.x, f01.y, f23.x, f23.y);
        }
    };

    int i = beg;
    int eo = g_eorig[i];
    float vv = vb[i];
    float4 tv[R];
    load_feats(g_esrc[i], tv);
    for (;;) {
        int inext = i + 1;
        bool more = inext < end;
        int eo2 = 0;
        float vv2 = 0.f;
        float4 tv2[R];
        if (more) {
            eo2 = g_eorig[inext];
            vv2 = vb[inext];
            load_feats(g_esrc[inext], tv2);
        }
        float a = __expf(vv - mx) * inv;
        if (lane == 0) alpha_out[eo * H + hh] = a;
#pragma unroll
        for (int r = 0; r < R; r++) {
            acc[r].x += a * tv[r].x;
            acc[r].y += a * tv[r].y;
            acc[r].z += a * tv[r].z;
            acc[r].w += a * tv[r].w;
        }
        if (!more) break;
        eo = eo2; vv = vv2;
#pragma unroll
        for (int r = 0; r < R; r++) tv[r] = tv2[r];
        i = inext;
    }

    /* epilogue: bias (+ELU), fp32 out or single fp16 out */
#pragma unroll
    for (int r = 0; r < R; r++) {
        int c = (lane + 32 * r) * 4;
        const float* bp = bias + hh * C + c;
        float4 o = acc[r];
        o.x += bp[0]; o.y += bp[1]; o.z += bp[2]; o.w += bp[3];
        if (ELU) {
            o.x = o.x > 0.f ? o.x : expm1f(o.x);
            o.y = o.y > 0.f ? o.y : expm1f(o.y);
            o.z = o.z > 0.f ? o.z : expm1f(o.z);
            o.w = o.w > 0.f ? o.w : expm1f(o.w);
        }
        if (SPLIT) {
            size_t base = (size_t)dst * (H * C) + hh * C + c;
            *(__half2*)(of16 + base)     = __floats2half2_rn(o.x, o.y);
            *(__half2*)(of16 + base + 2) = __floats2half2_rn(o.z, o.w);
        } else {
            float* op = aggout + (size_t)dst * (H * C) + hh * C;
            ((float4*)op)[lane + 32 * r] = o;
        }
    }
}

/* ------------------------- launch ------------------------- */
extern "C" void kernel_launch(void* const* d_in, const int* in_sizes, int n_in,
                              void* d_out, int out_size) {
    const float* x      = (const float*)d_in[0];
    const int*   ei     = (const int*)  d_in[1];
    const float* W1     = (const float*)d_in[2];
    const float* a_src1 = (const float*)d_in[3];
    const float* a_dst1 = (const float*)d_in[4];
    const float* b1     = (const float*)d_in[5];
    const float* W2     = (const float*)d_in[6];
    const float* a_src2 = (const float*)d_in[7];
    const float* a_dst2 = (const float*)d_in[8];
    const float* b2     = (const float*)d_in[9];
    float* out = (float*)d_out;

    float *as1, *ad1, *as2, *ad2;
    __half *h1f, *h2f, *xf, *w1h, *w2h, *a1f;
    cudaGetSymbolAddress((void**)&h1f,  g_h1f);
    cudaGetSymbolAddress((void**)&h2f,  g_h2f);
    cudaGetSymbolAddress((void**)&as1,  g_as1);
    cudaGetSymbolAddress((void**)&ad1,  g_ad1);
    cudaGetSymbolAddress((void**)&as2,  g_as2);
    cudaGetSymbolAddress((void**)&ad2,  g_ad2);
    cudaGetSymbolAddress((void**)&xf,   g_xf);
    cudaGetSymbolAddress((void**)&w1h,  g_w1h);
    cudaGetSymbolAddress((void**)&w2h,  g_w2h);
    cudaGetSymbolAddress((void**)&a1f,  g_a1f);

    /* second stream + fork/join events (created once, before first capture) */
    static cudaStream_t s2 = nullptr;
    static cudaEvent_t evF = nullptr, evJ = nullptr;
    if (!s2) {
        cudaStreamCreateWithFlags(&s2, cudaStreamNonBlocking);
        cudaEventCreateWithFlags(&evF, cudaEventDisableTiming);
        cudaEventCreateWithFlags(&evJ, cudaEventDisableTiming);
    }

    /* fork: CSR build + W2 convert run concurrently with x/W1 + gemm1 */
    cudaEventRecord(evF, 0);
    cudaStreamWaitEvent(s2, evF, 0);
    zero_counts<<<(N_NODES + 255) / 256, 256, 0, s2>>>();
    count_deg<<<(NE_TOT + 255) / 256, 256, 0, s2>>>(ei);
    scan_rowptr<<<1, 1024, 0, s2>>>();
    scatter_edges<<<(NE_TOT + 255) / 256, 256, 0, s2>>>(ei);
    cvt_w_t<<<(L1_F * OUT_CH + 255) / 256, 256, 0, s2>>>(W2, w2h, L1_F, OUT_CH);
    cudaEventRecord(evJ, s2);

    /* main stream: conversions, gemm1, attn1 */
    cvt_fp32<<<(N_NODES * IN_CH + 255) / 256, 256>>>(x, xf, N_NODES * IN_CH);
    cvt_w_t<<<(IN_CH * L1_F + 255) / 256, 256>>>(W1, w1h, IN_CH, L1_F);
    gemm_hmma<<<dim3(L1_F / 128, 157), 256>>>(xf, w1h, h1f, N_NODES, L1_F);
    attn_coef<HEADS, HID><<<(N_NODES * HEADS + 7) / 8, 256>>>(h1f, a_src1, a_dst1, as1, ad1);

    /* join: need CSR (and W2) before aggregation / gemm2 */
    cudaStreamWaitEvent(0, evJ, 0);
    fused_agg<HEADS, HID, true, true><<<(N_NODES * HEADS + 7) / 8, 256>>>(
        as1, ad1, h1f, b1, out + A1_OFF, nullptr, a1f);

    /* layer 2 */
    gemm_hmma<<<dim3(OUT_CH / 128, 157), 256>>>(a1f, w2h, h2f, N_NODES, OUT_CH);
    attn_coef<1, OUT_CH><<<(N_NODES + 7) / 8, 256>>>(h2f, a_src2, a_dst2, as2, ad2);
    fused_agg<1, OUT_CH, false, false><<<(N_NODES + 7) / 8, 256>>>(
        as2, ad2, h2f, b2, out + A2_OFF, out, nullptr);
}

// round 16
// speedup vs baseline: 1.6813x; 1.0756x over previous
#include <cuda_runtime.h>
#include <cuda_fp16.h>
#include <math.h>
#include <stdint.h>

#define N_NODES 20000
#define N_EDGES 320000
#define NE_TOT  (N_EDGES + N_NODES)   /* 340000 incl self loops */
#define IN_CH   512
#define HID     128
#define HEADS   4
#define OUT_CH  256
#define L1_F    (HEADS * HID)         /* 512 */

#define A1_OFF  (N_NODES * OUT_CH)            /* 5,120,000 */
#define A2_OFF  (A1_OFF + NE_TOT * HEADS)     /* 6,480,000 */

/* ------------------------- scratch (device globals) ------------------------- */
__device__ __half g_h1f[(size_t)N_NODES * L1_F];   /* h1, fp16 */
__device__ __half g_h2f[(size_t)N_NODES * OUT_CH]; /* h2, fp16 */
__device__ __half g_xf[(size_t)N_NODES * IN_CH];   /* x,  fp16 */
__device__ __half g_w1h[L1_F * IN_CH];             /* transposed [N][K], fp16 */
__device__ __half g_w2h[OUT_CH * L1_F];
__device__ __half g_a1f[(size_t)N_NODES * L1_F];   /* agg1, fp16 */
__device__ float g_as1[N_NODES * HEADS];
__device__ float g_ad1[N_NODES * HEADS];
__device__ float g_as2[N_NODES];
__device__ float g_ad2[N_NODES];
__device__ float g_vbuf[(size_t)NE_TOT * HEADS];   /* layer1: [edge][head] f4 */
__device__ int   g_counts[N_NODES];
__device__ int   g_cursor[N_NODES];
__device__ int   g_rowptr[N_NODES + 1];
__device__ int   g_esrc[NE_TOT];
__device__ int   g_eorig[NE_TOT];

/* ------------------------- helpers ------------------------- */
__device__ __forceinline__ uint32_t smem_u32(const void* p) {
    uint32_t a;
    asm("{ .reg .u64 t; cvta.to.shared.u64 t, %1; cvt.u32.u64 %0, t; }" : "=r"(a) : "l"(p));
    return a;
}
__device__ __forceinline__ void ldsm_x4(uint32_t& r0, uint32_t& r1, uint32_t& r2,
                                        uint32_t& r3, uint32_t addr) {
    asm volatile("ldmatrix.sync.aligned.m8n8.x4.shared.b16 {%0,%1,%2,%3}, [%4];"
                 : "=r"(r0), "=r"(r1), "=r"(r2), "=r"(r3) : "r"(addr));
}
__device__ __forceinline__ void mma_f16(float* d, const uint32_t* a, const uint32_t* b) {
    asm volatile("mma.sync.aligned.m16n8k16.row.col.f32.f16.f16.f32 "
                 "{%0,%1,%2,%3}, {%4,%5,%6,%7}, {%8,%9}, {%0,%1,%2,%3};"
                 : "+f"(d[0]), "+f"(d[1]), "+f"(d[2]), "+f"(d[3])
                 : "r"(a[0]), "r"(a[1]), "r"(a[2]), "r"(a[3]), "r"(b[0]), "r"(b[1]));
}
__device__ __forceinline__ void cpa16(uint32_t dst, const void* src) {
    asm volatile("cp.async.cg.shared.global [%0], [%1], 16;" :: "r"(dst), "l"(src));
}
#define CP_COMMIT() asm volatile("cp.async.commit_group;" ::: "memory")
#define CP_WAIT0()  asm volatile("cp.async.wait_group 0;" ::: "memory")

__device__ __forceinline__ float lrelu(float v) { return v > 0.f ? v : 0.2f * v; }

/* ------------------------- CSR construction ------------------------- */
__device__ __forceinline__ void edge_nodes(const int* __restrict__ ei, int e,
                                           int& src, int& dst) {
    if (e < N_EDGES) { src = ei[e]; dst = ei[N_EDGES + e]; }
    else             { src = dst = e - N_EDGES; }
}

__global__ void zero_counts() {
    int i = blockIdx.x * blockDim.x + threadIdx.x;
    if (i < N_NODES) { g_counts[i] = 0; g_cursor[i] = 0; }
}

__global__ void count_deg(const int* __restrict__ ei) {
    int e = blockIdx.x * blockDim.x + threadIdx.x;
    if (e >= NE_TOT) return;
    int src, dst;
    edge_nodes(ei, e, src, dst);
    atomicAdd(&g_counts[dst], 1);
}

__global__ void scan_rowptr() {
    __shared__ int wsum[32];
    __shared__ int s_carry;
    int tid = threadIdx.x, lane = tid & 31, wid = tid >> 5;
    if (tid == 0) { g_rowptr[0] = 0; s_carry = 0; }
    __syncthreads();
    for (int base = 0; base < N_NODES; base += 1024) {
        int i = base + tid;
        int v = (i < N_NODES) ? g_counts[i] : 0;
        int x = v;
#pragma unroll
        for (int o = 1; o < 32; o <<= 1) {
            int t = __shfl_up_sync(0xFFFFFFFFu, x, o);
            if (lane >= o) x += t;
        }
        if (lane == 31) wsum[wid] = x;
        __syncthreads();
        if (wid == 0) {
            int s = wsum[lane];
#pragma unroll
            for (int o = 1; o < 32; o <<= 1) {
                int t = __shfl_up_sync(0xFFFFFFFFu, s, o);
                if (lane >= o) s += t;
            }
            wsum[lane] = s;
        }
        __syncthreads();
        int inc = x + (wid > 0 ? wsum[wid - 1] : 0) + s_carry;
        if (i < N_NODES) g_rowptr[i + 1] = inc;
        __syncthreads();
        if (tid == 1023) s_carry = inc;
        __syncthreads();
    }
}

__global__ void scatter_edges(const int* __restrict__ ei) {
    int e = blockIdx.x * blockDim.x + threadIdx.x;
    if (e >= NE_TOT) return;
    int src, dst;
    edge_nodes(ei, e, src, dst);
    int pos = g_rowptr[dst] + atomicAdd(&g_cursor[dst], 1);
    g_esrc[pos]  = src;
    g_eorig[pos] = e;
}

/* ------------------------- fp32 -> fp16 converts ------------------------- */
__global__ void cvt_fp32(const float* __restrict__ in, __half* __restrict__ o, int n) {
    int i = blockIdx.x * blockDim.x + threadIdx.x;
    if (i >= n) return;
    o[i] = __float2half_rn(in[i]);
}

/* W [K][N] -> out [N][K] fp16 */
__global__ void cvt_w_t(const float* __restrict__ W,
                        __half* __restrict__ t, int K, int N) {
    int i = blockIdx.x * blockDim.x + threadIdx.x;
    if (i >= K * N) return;
    int k = i / N, n = i % N;
    t[n * K + k] = __float2half_rn(W[i]);
}

/* ------------------------- HMMA fp16 GEMM -------------------------
   C[M,N] = A*B^T; A fp16 [M,K], B fp16 [N,K]. K=512.
   CTA tile 128x128, 8 warps, 2-buffer cp.async, wait0. fp16 output. */
#define KSTAGES (512 / 16)    /* 32 */
#define SROW    24

__global__ __launch_bounds__(256)
void gemm_hmma(const __half* __restrict__ A, const __half* __restrict__ B,
               __half* __restrict__ Cf, int M, int N) {
    __shared__ __align__(16) __half sA[2][128][SROW];
    __shared__ __align__(16) __half sB[2][128][SROW];

    int tid = threadIdx.x, wid = tid >> 5, lane = tid & 31;
    int m0 = blockIdx.y * 128, n0 = blockIdx.x * 128;
    int wm = (wid >> 1) * 32;
    int wn = (wid & 1) * 64;

    int prow = tid >> 1, pseg = tid & 1;
    int agr = m0 + prow; if (agr >= M) agr = M - 1;
    const __half* pA = A + (size_t)agr * 512 + pseg * 8;
    const __half* pB = B + (size_t)(n0 + prow) * 512 + pseg * 8;
    uint32_t dA[2], dB[2];
#pragma unroll
    for (int b = 0; b < 2; b++) {
        dA[b] = smem_u32(&sA[b][prow][pseg * 8]);
        dB[b] = smem_u32(&sB[b][prow][pseg * 8]);
    }

    int a_row = (lane & 15), a_k = (lane >> 4) * 8;
    int b_nrow = ((lane >> 4) << 3) + (lane & 7), b_k = ((lane >> 3) & 1) * 8;
    uint32_t a_base = smem_u32(&sA[0][wm + a_row][a_k]);
    uint32_t b_base = smem_u32(&sB[0][wn + b_nrow][b_k]);
    const uint32_t BUF = 128 * SROW * 2;

    float acc[2][8][4];
#pragma unroll
    for (int i = 0; i < 2; i++)
#pragma unroll
        for (int j = 0; j < 8; j++)
#pragma unroll
            for (int q = 0; q < 4; q++) acc[i][j][q] = 0.f;

    cpa16(dA[0], pA);
    cpa16(dB[0], pB);
    CP_COMMIT();
    CP_WAIT0();
    __syncthreads();

    for (int t = 0; t < KSTAGES; t++) {
        int buf = t & 1;
        if (t + 1 < KSTAGES) {
            int nb = (t + 1) & 1, ko = (t + 1) * 16;
            cpa16(dA[nb], pA + ko);
            cpa16(dB[nb], pB + ko);
            CP_COMMIT();
        }

        uint32_t af[2][4];
#pragma unroll
        for (int ma = 0; ma < 2; ma++)
            ldsm_x4(af[ma][0], af[ma][1], af[ma][2], af[ma][3],
                    a_base + buf * BUF + ma * 16 * SROW * 2);
        uint32_t bf[4][4];
#pragma unroll
        for (int g = 0; g < 4; g++)
            ldsm_x4(bf[g][0], bf[g][1], bf[g][2], bf[g][3],
                    b_base + buf * BUF + g * 16 * SROW * 2);

#pragma unroll
        for (int ma = 0; ma < 2; ma++)
#pragma unroll
            for (int g = 0; g < 4; g++)
#pragma unroll
                for (int h = 0; h < 2; h++)
                    mma_f16(acc[ma][g * 2 + h], af[ma], &bf[g][h * 2]);

        CP_WAIT0();
        __syncthreads();
    }

    int lg = lane >> 2, lt = lane & 3;
#pragma unroll
    for (int ma = 0; ma < 2; ma++) {
        int mrow0 = m0 + wm + ma * 16 + lg;
#pragma unroll
        for (int nb = 0; nb < 8; nb++) {
            int n = n0 + wn + nb * 8 + lt * 2;
            float* d = acc[ma][nb];
            if (mrow0 < M)
                *(__half2*)(Cf + (size_t)mrow0 * N + n) = __floats2half2_rn(d[0], d[1]);
            if (mrow0 + 8 < M)
                *(__half2*)(Cf + (size_t)(mrow0 + 8) * N + n) = __floats2half2_rn(d[2], d[3]);
        }
    }
}

/* ------------------------- attention coefficients (fp16 h) ----------------- */
template <int H, int C>
__global__ void attn_coef(const __half* __restrict__ h,
                          const float* __restrict__ a_src,
                          const float* __restrict__ a_dst,
                          float* __restrict__ as, float* __restrict__ ad) {
    int gw = (blockIdx.x * blockDim.x + threadIdx.x) >> 5;
    int lane = threadIdx.x & 31;
    if (gw >= N_NODES * H) return;
    int n = gw / H, hh = gw % H;
    const __half2* hp = (const __half2*)(h + (size_t)n * (H * C) + hh * C);
    const float* sp = a_src + hh * C;
    const float* dp = a_dst + hh * C;
    float s = 0.f, d = 0.f;
#pragma unroll
    for (int r = 0; r < C / 64; r++) {
        int c2 = lane + 32 * r;
        float2 f = __half22float2(hp[c2]);
        s += f.x * sp[c2 * 2] + f.y * sp[c2 * 2 + 1];
        d += f.x * dp[c2 * 2] + f.y * dp[c2 * 2 + 1];
    }
#pragma unroll
    for (int o = 16; o; o >>= 1) {
        s += __shfl_xor_sync(0xFFFFFFFFu, s, o);
        d += __shfl_xor_sync(0xFFFFFFFFu, d, o);
    }
    if (lane == 0) { as[gw] = s; ad[gw] = d; }
}

/* ------------------------- layer-1 fused softmax+aggregate: warp per dst ----
   All 4 heads per warp. Lane l handles head l>>3, channels (l&7)*16..+15 within
   that head's 128 (flattened f = l*16..l*16+15). vbuf stored [edge] float4. */
__global__ __launch_bounds__(256)
void fused_agg_mh(const float* __restrict__ as, const float* __restrict__ ad,
                  const __half* __restrict__ hf, const float* __restrict__ bias,
                  float* __restrict__ alpha_out, __half* __restrict__ of16) {
    int gw = (blockIdx.x * blockDim.x + threadIdx.x) >> 5;
    int lane = threadIdx.x & 31;
    if (gw >= N_NODES) return;
    int dst = gw;
    int beg = g_rowptr[dst], end = g_rowptr[dst + 1];
    float4 adv = *(const float4*)(ad + dst * 4);
    float4* vb = (float4*)g_vbuf;

    /* pass 1: logits for all 4 heads, store float4, track per-head max */
    float4 mx = make_float4(-1e30f, -1e30f, -1e30f, -1e30f);
    for (int i = beg + lane; i < end; i += 32) {
        float4 a4 = *(const float4*)(as + g_esrc[i] * 4);
        float4 v;
        v.x = lrelu(a4.x + adv.x);
        v.y = lrelu(a4.y + adv.y);
        v.z = lrelu(a4.z + adv.z);
        v.w = lrelu(a4.w + adv.w);
        vb[i] = v;
        mx.x = fmaxf(mx.x, v.x); mx.y = fmaxf(mx.y, v.y);
        mx.z = fmaxf(mx.z, v.z); mx.w = fmaxf(mx.w, v.w);
    }
#pragma unroll
    for (int o = 16; o; o >>= 1) {
        mx.x = fmaxf(mx.x, __shfl_xor_sync(0xFFFFFFFFu, mx.x, o));
        mx.y = fmaxf(mx.y, __shfl_xor_sync(0xFFFFFFFFu, mx.y, o));
        mx.z = fmaxf(mx.z, __shfl_xor_sync(0xFFFFFFFFu, mx.z, o));
        mx.w = fmaxf(mx.w, __shfl_xor_sync(0xFFFFFFFFu, mx.w, o));
    }

    /* pass 2: per-head denom */
    float4 sm = make_float4(0.f, 0.f, 0.f, 0.f);
    for (int i = beg + lane; i < end; i += 32) {
        float4 v = vb[i];
        sm.x += __expf(v.x - mx.x); sm.y += __expf(v.y - mx.y);
        sm.z += __expf(v.z - mx.z); sm.w += __expf(v.w - mx.w);
    }
#pragma unroll
    for (int o = 16; o; o >>= 1) {
        sm.x += __shfl_xor_sync(0xFFFFFFFFu, sm.x, o);
        sm.y += __shfl_xor_sync(0xFFFFFFFFu, sm.y, o);
        sm.z += __shfl_xor_sync(0xFFFFFFFFu, sm.z, o);
        sm.w += __shfl_xor_sync(0xFFFFFFFFu, sm.w, o);
    }

    /* lane's head constants */
    int hsel = lane >> 3;
    float mxa[4] = { mx.x, mx.y, mx.z, mx.w };
    float sma[4] = { sm.x, sm.y, sm.z, sm.w };
    float mxh = mxa[hsel];
    float invh = 1.f / sma[hsel];
    const float* vbh = (const float*)g_vbuf + hsel;   /* stride 4 floats */

    /* pass 3: alpha + gather-accumulate, depth-2 pipeline.
       Lane reads 32B (16 halves) at flattened offset lane*16 of the 512-wide row. */
    float acc[16];
#pragma unroll
    for (int j = 0; j < 16; j++) acc[j] = 0.f;

    int i = beg;
    int eo = g_eorig[i];
    float vh = vbh[(size_t)i * 4];
    uint4 u0, u1;
    {
        const uint4* hp = (const uint4*)(hf + (size_t)g_esrc[i] * 512 + lane * 16);
        u0 = hp[0]; u1 = hp[1];
    }
    for (;;) {
        int inext = i + 1;
        bool more = inext < end;
        int eo2 = 0;
        float vh2 = 0.f;
        uint4 v0, v1;
        if (more) {
            eo2 = g_eorig[inext];
            vh2 = vbh[(size_t)inext * 4];
            const uint4* hp2 = (const uint4*)(hf + (size_t)g_esrc[inext] * 512 + lane * 16);
            v0 = hp2[0]; v1 = hp2[1];
        }
        float a = __expf(vh - mxh) * invh;
        if ((lane & 7) == 0) alpha_out[eo * 4 + hsel] = a;
        const uint32_t* uu = (const uint32_t*)&u0;
#pragma unroll
        for (int q = 0; q < 4; q++) {
            float2 f = __half22float2(*(const __half2*)&uu[q]);
            acc[q * 2 + 0] += a * f.x;
            acc[q * 2 + 1] += a * f.y;
        }
        const uint32_t* uv = (const uint32_t*)&u1;
#pragma unroll
        for (int q = 0; q < 4; q++) {
            float2 f = __half22float2(*(const __half2*)&uv[q]);
            acc[8 + q * 2 + 0] += a * f.x;
            acc[8 + q * 2 + 1] += a * f.y;
        }
        if (!more) break;
        eo = eo2; vh = vh2; u0 = v0; u1 = v1;
        i = inext;
    }

    /* epilogue: bias + ELU + fp16 store (16 channels at f = lane*16) */
    const float* bp = bias + lane * 16;
    __half2 ho[8];
#pragma unroll
    for (int q = 0; q < 8; q++) {
        float o0 = acc[q * 2 + 0] + bp[q * 2 + 0];
        float o1 = acc[q * 2 + 1] + bp[q * 2 + 1];
        o0 = o0 > 0.f ? o0 : expm1f(o0);
        o1 = o1 > 0.f ? o1 : expm1f(o1);
        ho[q] = __floats2half2_rn(o0, o1);
    }
    uint4* op = (uint4*)(of16 + (size_t)dst * 512 + lane * 16);
    op[0] = *(uint4*)&ho[0];
    op[1] = *(uint4*)&ho[4];
}

/* ------------------------- layer-2 fused softmax + aggregate --------------- */
template <int H, int C>
__global__ __launch_bounds__(256)
void fused_agg(const float* __restrict__ as, const float* __restrict__ ad,
               const __half* __restrict__ hfeat_h, const float* __restrict__ bias,
               float* __restrict__ alpha_out, float* __restrict__ aggout) {
    int gw = (blockIdx.x * blockDim.x + threadIdx.x) >> 5;
    int lane = threadIdx.x & 31;
    if (gw >= N_NODES * H) return;
    int dst = gw / H, hh = gw % H;

    int beg = g_rowptr[dst], end = g_rowptr[dst + 1];
    float adv = ad[dst * H + hh];
    float* vb = g_vbuf;

    float mx = -1e30f;
    for (int i = beg + lane; i < end; i += 32) {
        float v = lrelu(as[g_esrc[i] * H + hh] + adv);
        vb[i] = v;
        mx = fmaxf(mx, v);
    }
#pragma unroll
    for (int o = 16; o; o >>= 1) mx = fmaxf(mx, __shfl_xor_sync(0xFFFFFFFFu, mx, o));

    float sm = 0.f;
    for (int i = beg + lane; i < end; i += 32) sm += __expf(vb[i] - mx);
#pragma unroll
    for (int o = 16; o; o >>= 1) sm += __shfl_xor_sync(0xFFFFFFFFu, sm, o);
    float inv = 1.f / sm;

    constexpr int R = C / 128;
    float4 acc[R];
#pragma unroll
    for (int r = 0; r < R; r++) acc[r] = make_float4(0.f, 0.f, 0.f, 0.f);

    auto load_feats = [&](int s, float4* t) {
        const uint2* hp = (const uint2*)(hfeat_h + (size_t)s * (H * C) + hh * C);
#pragma unroll
        for (int r = 0; r < R; r++) {
            uint2 u = hp[lane + 32 * r];
            float2 f01 = __half22float2(*(__half2*)&u.x);
            float2 f23 = __half22float2(*(__half2*)&u.y);
            t[r] = make_float4(f01.x, f01.y, f23.x, f23.y);
        }
    };

    int i = beg;
    int eo = g_eorig[i];
    float vv = vb[i];
    float4 tv[R];
    load_feats(g_esrc[i], tv);
    for (;;) {
        int inext = i + 1;
        bool more = inext < end;
        int eo2 = 0;
        float vv2 = 0.f;
        float4 tv2[R];
        if (more) {
            eo2 = g_eorig[inext];
            vv2 = vb[inext];
            load_feats(g_esrc[inext], tv2);
        }
        float a = __expf(vv - mx) * inv;
        if (lane == 0) alpha_out[eo * H + hh] = a;
#pragma unroll
        for (int r = 0; r < R; r++) {
            acc[r].x += a * tv[r].x;
            acc[r].y += a * tv[r].y;
            acc[r].z += a * tv[r].z;
            acc[r].w += a * tv[r].w;
        }
        if (!more) break;
        eo = eo2; vv = vv2;
#pragma unroll
        for (int r = 0; r < R; r++) tv[r] = tv2[r];
        i = inext;
    }

#pragma unroll
    for (int r = 0; r < R; r++) {
        int c = (lane + 32 * r) * 4;
        const float* bp = bias + hh * C + c;
        float4 o = acc[r];
        o.x += bp[0]; o.y += bp[1]; o.z += bp[2]; o.w += bp[3];
        float* op = aggout + (size_t)dst * (H * C) + hh * C;
        ((float4*)op)[lane + 32 * r] = o;
    }
}

/* ------------------------- launch ------------------------- */
extern "C" void kernel_launch(void* const* d_in, const int* in_sizes, int n_in,
                              void* d_out, int out_size) {
    const float* x      = (const float*)d_in[0];
    const int*   ei     = (const int*)  d_in[1];
    const float* W1     = (const float*)d_in[2];
    const float* a_src1 = (const float*)d_in[3];
    const float* a_dst1 = (const float*)d_in[4];
    const float* b1     = (const float*)d_in[5];
    const float* W2     = (const float*)d_in[6];
    const float* a_src2 = (const float*)d_in[7];
    const float* a_dst2 = (const float*)d_in[8];
    const float* b2     = (const float*)d_in[9];
    float* out = (float*)d_out;

    float *as1, *ad1, *as2, *ad2;
    __half *h1f, *h2f, *xf, *w1h, *w2h, *a1f;
    cudaGetSymbolAddress((void**)&h1f,  g_h1f);
    cudaGetSymbolAddress((void**)&h2f,  g_h2f);
    cudaGetSymbolAddress((void**)&as1,  g_as1);
    cudaGetSymbolAddress((void**)&ad1,  g_ad1);
    cudaGetSymbolAddress((void**)&as2,  g_as2);
    cudaGetSymbolAddress((void**)&ad2,  g_ad2);
    cudaGetSymbolAddress((void**)&xf,   g_xf);
    cudaGetSymbolAddress((void**)&w1h,  g_w1h);
    cudaGetSymbolAddress((void**)&w2h,  g_w2h);
    cudaGetSymbolAddress((void**)&a1f,  g_a1f);

    static cudaStream_t s2 = nullptr;
    static cudaEvent_t evF = nullptr, evJ = nullptr;
    if (!s2) {
        cudaStreamCreateWithFlags(&s2, cudaStreamNonBlocking);
        cudaEventCreateWithFlags(&evF, cudaEventDisableTiming);
        cudaEventCreateWithFlags(&evJ, cudaEventDisableTiming);
    }

    /* fork: CSR build + W2 convert run concurrently with x/W1 + gemm1 */
    cudaEventRecord(evF, 0);
    cudaStreamWaitEvent(s2, evF, 0);
    zero_counts<<<(N_NODES + 255) / 256, 256, 0, s2>>>();
    count_deg<<<(NE_TOT + 255) / 256, 256, 0, s2>>>(ei);
    scan_rowptr<<<1, 1024, 0, s2>>>();
    scatter_edges<<<(NE_TOT + 255) / 256, 256, 0, s2>>>(ei);
    cvt_w_t<<<(L1_F * OUT_CH + 255) / 256, 256, 0, s2>>>(W2, w2h, L1_F, OUT_CH);
    cudaEventRecord(evJ, s2);

    /* main stream: conversions, gemm1, attn1 */
    cvt_fp32<<<(N_NODES * IN_CH + 255) / 256, 256>>>(x, xf, N_NODES * IN_CH);
    cvt_w_t<<<(IN_CH * L1_F + 255) / 256, 256>>>(W1, w1h, IN_CH, L1_F);
    gemm_hmma<<<dim3(L1_F / 128, 157), 256>>>(xf, w1h, h1f, N_NODES, L1_F);
    attn_coef<HEADS, HID><<<(N_NODES * HEADS + 7) / 8, 256>>>(h1f, a_src1, a_dst1, as1, ad1);

    /* join: need CSR (and W2) before aggregation / gemm2 */
    cudaStreamWaitEvent(0, evJ, 0);
    fused_agg_mh<<<(N_NODES + 7) / 8, 256>>>(as1, ad1, h1f, b1, out + A1_OFF, a1f);

    /* layer 2 */
    gemm_hmma<<<dim3(OUT_CH / 128, 157), 256>>>(a1f, w2h, h2f, N_NODES, OUT_CH);
    attn_coef<1, OUT_CH><<<(N_NODES + 7) / 8, 256>>>(h2f, a_src2, a_dst2, as2, ad2);
    fused_agg<1, OUT_CH><<<(N_NODES + 7) / 8, 256>>>(
        as2, ad2, h2f, b2, out + A2_OFF, out);
}